// round 4
// baseline (speedup 1.0000x reference)
#include <cuda_runtime.h>
#include <math.h>

#define NN   50000
#define EE   200000
#define FIN  128
#define HID  1024
#define CLS  16
#define EPSV 1e-5f

// ---------------- scratch (static __device__, no allocs) ----------------
__device__ float g_deg[NN];
__device__ int   g_cnt[NN];
__device__ float g_dinv[NN];
__device__ float g_cntinv[NN];
__device__ int   g_rowptr[NN + 1];
__device__ int   g_fill[NN];
__device__ int   g_col[EE];
__device__ float g_ew[EE];
__device__ int   g_is64;

__device__ __align__(16) float g_Xcat[(size_t)NN * 512];   // [N, 4*128]
__device__ __align__(16) float g_T1[(size_t)NN * HID];
__device__ __align__(16) float g_T2[(size_t)NN * HID];
__device__ __align__(16) float g_Hcat[(size_t)NN * 4096];  // [N, 4*1024]
__device__ __align__(16) float g_Z[(size_t)NN * 64];       // [N, 4*16]
__device__ __align__(16) float g_U[(size_t)NN * CLS];
__device__ __align__(16) float g_V[(size_t)NN * CLS];
__device__ float g_sums[HID];
__device__ float g_sq[HID];

// compile-time buffer selector -> direct global references
#define B_XCAT 0
#define B_T1   1
#define B_T2   2
#define B_HCAT 3
#define B_Z    4
#define B_U    5
#define B_V    6
template <int S> __device__ __forceinline__ float* bufsel() {
    if (S == B_XCAT) return g_Xcat;
    if (S == B_T1)   return g_T1;
    if (S == B_T2)   return g_T2;
    if (S == B_HCAT) return g_Hcat;
    if (S == B_Z)    return g_Z;
    if (S == B_U)    return g_U;
    return g_V;
}

// ---------------- edge index access (int32 expected; int64 tolerated) ----
__global__ void k_detect(const int* __restrict__ ei32) {
    int z = 0;
    for (int i = 1; i < 128; i += 2) z |= ei32[i];
    g_is64 = (z == 0) ? 1 : 0;   // odd words all zero => int64 little-endian
}
__device__ __forceinline__ int edge_at(const void* ei, int idx) {
    int v;
    if (g_is64) v = (int)((const long long*)ei)[idx];
    else        v = ((const int*)ei)[idx];
    if ((unsigned)v >= NN) v = 0;   // never fault on a wrong guess
    return v;
}

// ---------------- graph preprocessing ----------------
__global__ void k_zero_pre() {
    int i = blockIdx.x * blockDim.x + threadIdx.x;
    if (i < NN) { g_deg[i] = 0.f; g_cnt[i] = 0; g_fill[i] = 0; }
}
__global__ void k_zero_stats() {
    int i = blockIdx.x * blockDim.x + threadIdx.x;
    if (i < HID) { g_sums[i] = 0.f; g_sq[i] = 0.f; }
}
__global__ void k_deg(const void* __restrict__ ei, const float* __restrict__ w) {
    int e = blockIdx.x * blockDim.x + threadIdx.x;
    if (e >= EE) return;
    int d = edge_at(ei, EE + e);
    atomicAdd(&g_deg[d], w[e]);
    atomicAdd(&g_cnt[d], 1);
}
__global__ void k_norm() {
    int i = blockIdx.x * blockDim.x + threadIdx.x;
    if (i >= NN) return;
    float dg = g_deg[i];
    g_dinv[i] = dg > 0.f ? rsqrtf(dg) : 0.f;
    int c = g_cnt[i];
    g_cntinv[i] = c > 0 ? 1.f / (float)c : 0.f;
}
__global__ void k_scan() {   // exclusive prefix sum of g_cnt -> g_rowptr
    __shared__ int sh[1024];
    __shared__ int carry;
    int tid = threadIdx.x;
    if (tid == 0) carry = 0;
    __syncthreads();
    for (int base = 0; base < NN; base += 1024) {
        int idx = base + tid;
        int v = (idx < NN) ? g_cnt[idx] : 0;
        sh[tid] = v;
        __syncthreads();
        for (int off = 1; off < 1024; off <<= 1) {
            int t = (tid >= off) ? sh[tid - off] : 0;
            __syncthreads();
            sh[tid] += t;
            __syncthreads();
        }
        int c0 = carry;
        if (idx < NN) g_rowptr[idx] = c0 + sh[tid] - v;
        __syncthreads();
        if (tid == 0) carry = c0 + sh[1023];
        __syncthreads();
    }
    if (tid == 0) g_rowptr[NN] = carry;
}
__global__ void k_fill(const void* __restrict__ ei, const float* __restrict__ w) {
    int e = blockIdx.x * blockDim.x + threadIdx.x;
    if (e >= EE) return;
    int s = edge_at(ei, e);
    int d = edge_at(ei, EE + e);
    int pos = g_rowptr[d] + atomicAdd(&g_fill[d], 1);
    if (pos < EE) {
        g_col[pos] = s;
        g_ew[pos]  = g_dinv[s] * w[e] * g_dinv[d] * g_cntinv[d];
    }
}

// ---------------- propagation (gather SpMM over CSR) ----------------
template <int INSEL, int OUTSEL>
__global__ void k_spmm(int inoff, int ldin, int outoff, int ldout, int d, int shift) {
    const float* hin = bufsel<INSEL>() + inoff;
    float* hout = bufsel<OUTSEL>() + outoff;
    long long t = (long long)blockIdx.x * blockDim.x + threadIdx.x;
    long long total = (long long)NN * d;
    if (t >= total) return;
    int i = (int)(t >> shift);
    int f = (int)(t & (d - 1));
    int s = g_rowptr[i], e = g_rowptr[i + 1];
    float acc = 0.f;
    for (int j = s; j < e; j++)
        acc += g_ew[j] * __ldg(&hin[(size_t)g_col[j] * ldin + f]);
    hout[(size_t)i * ldout + f] = acc;
}

__global__ void k_copy_x(const float* __restrict__ x) {
    int t = blockIdx.x * blockDim.x + threadIdx.x;
    if (t >= NN * FIN) return;
    int n = t >> 7, f = t & 127;
    g_Xcat[(size_t)n * 512 + f] = x[t];
}

// ---------------- fp32 tiled GEMM: C = A@B (+bias +ELU) ----------------
// 128x128 tile, BK=16, 256 threads, 8x8 microtile
template <int ASEL, int CSEL>
__global__ __launch_bounds__(256, 2)
void k_gemm(int lda, const float* __restrict__ B, int ldb,
            int ldc, int M, int Kd,
            const float* __restrict__ bias, int do_elu) {
    const float* A = bufsel<ASEL>();
    float* C = bufsel<CSEL>();
    __shared__ float As[16][128];
    __shared__ float Bs[16][128];
    const int tid  = threadIdx.x;
    const int row0 = blockIdx.y * 128;
    const int col0 = blockIdx.x * 128;

    const int a_r = tid >> 2;         // 0..63
    const int a_c = (tid & 3) * 4;    // 0,4,8,12
    const int b_r = tid >> 5;         // 0..7
    const int b_c = (tid & 31) * 4;   // 0..124

    const int ty = tid >> 4;          // 0..15
    const int tx = tid & 15;          // 0..15

    float acc[8][8];
#pragma unroll
    for (int i = 0; i < 8; i++)
#pragma unroll
        for (int j = 0; j < 8; j++) acc[i][j] = 0.f;

    for (int kk = 0; kk < Kd; kk += 16) {
#pragma unroll
        for (int s = 0; s < 2; s++) {
            int r = a_r + s * 64;
            float4 v = make_float4(0.f, 0.f, 0.f, 0.f);
            if (row0 + r < M)
                v = *reinterpret_cast<const float4*>(&A[(size_t)(row0 + r) * lda + kk + a_c]);
            As[a_c + 0][r] = v.x;
            As[a_c + 1][r] = v.y;
            As[a_c + 2][r] = v.z;
            As[a_c + 3][r] = v.w;
        }
#pragma unroll
        for (int s = 0; s < 2; s++) {
            int r = b_r + s * 8;
            float4 v = *reinterpret_cast<const float4*>(&B[(size_t)(kk + r) * ldb + col0 + b_c]);
            *reinterpret_cast<float4*>(&Bs[r][b_c]) = v;
        }
        __syncthreads();
#pragma unroll
        for (int k = 0; k < 16; k++) {
            float4 a0 = *reinterpret_cast<const float4*>(&As[k][ty * 8]);
            float4 a1 = *reinterpret_cast<const float4*>(&As[k][ty * 8 + 4]);
            float4 b0 = *reinterpret_cast<const float4*>(&Bs[k][tx * 8]);
            float4 b1 = *reinterpret_cast<const float4*>(&Bs[k][tx * 8 + 4]);
            float ra[8] = {a0.x, a0.y, a0.z, a0.w, a1.x, a1.y, a1.z, a1.w};
            float rb[8] = {b0.x, b0.y, b0.z, b0.w, b1.x, b1.y, b1.z, b1.w};
#pragma unroll
            for (int i = 0; i < 8; i++)
#pragma unroll
                for (int j = 0; j < 8; j++)
                    acc[i][j] += ra[i] * rb[j];
        }
        __syncthreads();
    }

#pragma unroll
    for (int i = 0; i < 8; i++) {
        int r = row0 + ty * 8 + i;
        if (r >= M) continue;
#pragma unroll
        for (int j = 0; j < 8; j++) {
            int c = col0 + tx * 8 + j;
            float v = acc[i][j] + bias[c];
            if (do_elu) v = v > 0.f ? v : expm1f(v);
            C[(size_t)r * ldc + c] = v;
        }
    }
}

// ---------------- GraphNorm ----------------
#define RPB 512
template <int XSEL>
__global__ void k_colsum(int ld) {
    const float* X = bufsel<XSEL>();
    int c  = blockIdx.x * blockDim.x + threadIdx.x;
    int r0 = blockIdx.y * RPB;
    int r1 = min(r0 + RPB, NN);
    float acc = 0.f;
    for (int r = r0; r < r1; r++) acc += X[(size_t)r * ld + c];
    atomicAdd(&g_sums[c], acc);
}
template <int XSEL, int YSEL>
__global__ void k_center(int ldx, int yoff, int ldy, const float* __restrict__ a) {
    const float* X = bufsel<XSEL>();
    float* Y = bufsel<YSEL>() + yoff;
    int c  = blockIdx.x * blockDim.x + threadIdx.x;
    int r0 = blockIdx.y * RPB;
    int r1 = min(r0 + RPB, NN);
    float am = a[c] * (g_sums[c] * (1.f / NN));
    float acc = 0.f;
    for (int r = r0; r < r1; r++) {
        float y = X[(size_t)r * ldx + c] - am;
        Y[(size_t)r * ldy + c] = y;
        acc += y * y;
    }
    atomicAdd(&g_sq[c], acc);
}
template <int YSEL>
__global__ void k_gnfinal(int yoff, int ld,
                          const float* __restrict__ g, const float* __restrict__ be) {
    float* Y = bufsel<YSEL>() + yoff;
    long long t = (long long)blockIdx.x * blockDim.x + threadIdx.x;
    if (t >= (long long)NN * HID) return;
    int c = (int)(t & (HID - 1));
    size_t idx = (size_t)(t >> 10) * ld + c;
    float s = g[c] * rsqrtf(g_sq[c] * (1.f / NN) + EPSV);
    Y[idx] = Y[idx] * s + be[c];
}

// ---------------- layer 3: project then Horner-propagate ----------------
__global__ void k_zproj(const float* __restrict__ W3) {
    int t = blockIdx.x * blockDim.x + threadIdx.x;
    if (t >= NN * 64) return;
    int n = t >> 6, o = t & 63;
    int k = o >> 4, c = o & 15;
    const float* hr = g_T1 + (size_t)n * HID;
    const float* wp = W3 + (size_t)k * HID * CLS + c;
    float acc = 0.f;
#pragma unroll 8
    for (int i = 0; i < HID; i++)
        acc += hr[i] * __ldg(&wp[(size_t)i * CLS]);
    g_Z[(size_t)n * 64 + o] = acc;
}
template <int USEL>
__global__ void k_add16(int zoff) {
    float* U = bufsel<USEL>();
    int t = blockIdx.x * blockDim.x + threadIdx.x;
    if (t >= NN * CLS) return;
    int n = t >> 4, c = t & 15;
    U[t] += g_Z[(size_t)n * 64 + zoff + c];
}
__global__ void k_final(float* __restrict__ out, const float* __restrict__ b3) {
    int t = blockIdx.x * blockDim.x + threadIdx.x;
    if (t >= NN * CLS) return;
    int n = t >> 4, c = t & 15;
    out[t] = g_U[t] + g_Z[(size_t)n * 64 + c] + b3[c];
}

// ---------------- host launcher ----------------
extern "C" void kernel_launch(void* const* d_in, const int* in_sizes, int n_in,
                              void* d_out, int out_size) {
    const float* x   = (const float*)d_in[0];
    const void*  ei  = d_in[1];                 // int32 expected (JAX canonicalized)
    const float* w   = (const float*)d_in[2];
    const float* W1  = (const float*)d_in[3];
    const float* b1  = (const float*)d_in[4];
    const float* g1  = (const float*)d_in[5];
    const float* be1 = (const float*)d_in[6];
    const float* a1  = (const float*)d_in[7];
    const float* W2  = (const float*)d_in[8];
    const float* b2  = (const float*)d_in[9];
    const float* g2  = (const float*)d_in[10];
    const float* be2 = (const float*)d_in[11];
    const float* a2  = (const float*)d_in[12];
    const float* W3  = (const float*)d_in[13];
    const float* b3  = (const float*)d_in[14];
    float* out = (float*)d_out;

    const int TB = 256;
    // --- graph preprocessing: degrees, norms, CSR ---
    k_detect<<<1, 1>>>((const int*)ei);
    k_zero_pre<<<(NN + TB - 1) / TB, TB>>>();
    k_deg<<<(EE + TB - 1) / TB, TB>>>(ei, w);
    k_norm<<<(NN + TB - 1) / TB, TB>>>();
    k_scan<<<1, 1024>>>();
    k_fill<<<(EE + TB - 1) / TB, TB>>>(ei, w);

    // --- layer 1: hop-concat (d=128), one GEMM [N,512]@[512,1024] ---
    k_copy_x<<<(NN * FIN + TB - 1) / TB, TB>>>(x);
    for (int k = 1; k <= 3; k++)
        k_spmm<B_XCAT, B_XCAT><<<(int)(((long long)NN * 128 + TB - 1) / TB), TB>>>(
            (k - 1) * 128, 512, k * 128, 512, 128, 7);
    k_gemm<B_XCAT, B_T1><<<dim3(HID / 128, (NN + 127) / 128), 256>>>(
        512, W1, HID, HID, NN, 512, b1, 1);

    // --- GraphNorm 1 -> Hcat slice 0 ---
    k_zero_stats<<<(HID + TB - 1) / TB, TB>>>();
    k_colsum<B_T1><<<dim3(HID / TB, (NN + RPB - 1) / RPB), TB>>>(HID);
    k_center<B_T1, B_HCAT><<<dim3(HID / TB, (NN + RPB - 1) / RPB), TB>>>(HID, 0, 4096, a1);
    k_gnfinal<B_HCAT><<<(int)(((long long)NN * HID + TB - 1) / TB), TB>>>(0, 4096, g1, be1);

    // --- layer 2: hop-concat (d=1024), one GEMM [N,4096]@[4096,1024] ---
    for (int k = 1; k <= 3; k++)
        k_spmm<B_HCAT, B_HCAT><<<(int)(((long long)NN * 1024 + TB - 1) / TB), TB>>>(
            (k - 1) * 1024, 4096, k * 1024, 4096, 1024, 10);
    k_gemm<B_HCAT, B_T2><<<dim3(HID / 128, (NN + 127) / 128), 256>>>(
        4096, W2, HID, HID, NN, 4096, b2, 1);

    // --- GraphNorm 2 -> T1 (h2) ---
    k_zero_stats<<<(HID + TB - 1) / TB, TB>>>();
    k_colsum<B_T2><<<dim3(HID / TB, (NN + RPB - 1) / RPB), TB>>>(HID);
    k_center<B_T2, B_T1><<<dim3(HID / TB, (NN + RPB - 1) / RPB), TB>>>(HID, 0, HID, a2);
    k_gnfinal<B_T1><<<(int)(((long long)NN * HID + TB - 1) / TB), TB>>>(0, HID, g2, be2);

    // --- layer 3: project first (z_k = h2 @ W3[k], [N,16]), then Horner over A ---
    k_zproj<<<(NN * 64 + TB - 1) / TB, TB>>>(W3);
    // out = z0 + A(z1 + A(z2 + A z3))
    k_spmm<B_Z, B_U><<<(NN * CLS + TB - 1) / TB, TB>>>(48, 64, 0, 16, 16, 4);  // U = A z3
    k_add16<B_U><<<(NN * CLS + TB - 1) / TB, TB>>>(32);                        // U += z2
    k_spmm<B_U, B_V><<<(NN * CLS + TB - 1) / TB, TB>>>(0, 16, 0, 16, 16, 4);   // V = A U
    k_add16<B_V><<<(NN * CLS + TB - 1) / TB, TB>>>(16);                        // V += z1
    k_spmm<B_V, B_U><<<(NN * CLS + TB - 1) / TB, TB>>>(0, 16, 0, 16, 16, 4);   // U = A V
    k_final<<<(NN * CLS + TB - 1) / TB, TB>>>(out, b3);                        // out = U + z0 + b3
}

// round 7
// speedup vs baseline: 1.2741x; 1.2741x over previous
#include <cuda_runtime.h>
#include <cuda_bf16.h>
#include <mma.h>
#include <math.h>

using namespace nvcuda;

#define NN   50000
#define EE   200000
#define FIN  128
#define HID  1024
#define CLS  16
#define EPSV 1e-5f

// ---------------- scratch (static __device__, no allocs) ----------------
__device__ float g_deg[NN];
__device__ int   g_cnt[NN];
__device__ float g_dinv[NN];
__device__ float g_cntinv[NN];
__device__ int   g_rowptr[NN + 1];
__device__ int   g_fill[NN];
__device__ int   g_col[EE];
__device__ float g_ew[EE];
__device__ int   g_is64;

__device__ __align__(16) float g_Xcat[(size_t)NN * 512];   // [N, 4*128]
__device__ __align__(16) float g_T1[(size_t)NN * HID];
__device__ __align__(16) float g_T2[(size_t)NN * HID];
__device__ __align__(16) float g_Hcat[(size_t)NN * 4096];  // [N, 4*1024]
__device__ __align__(16) float g_Z[(size_t)NN * 64];       // [N, 4*16]
__device__ __align__(16) float g_U[(size_t)NN * CLS];
__device__ __align__(16) float g_V[(size_t)NN * CLS];
__device__ float g_sums[HID];
__device__ float g_sq[HID];

// compile-time buffer selector -> direct global references
#define B_XCAT 0
#define B_T1   1
#define B_T2   2
#define B_HCAT 3
#define B_Z    4
#define B_U    5
#define B_V    6
template <int S> __device__ __forceinline__ float* bufsel() {
    if (S == B_XCAT) return g_Xcat;
    if (S == B_T1)   return g_T1;
    if (S == B_T2)   return g_T2;
    if (S == B_HCAT) return g_Hcat;
    if (S == B_Z)    return g_Z;
    if (S == B_U)    return g_U;
    return g_V;
}

// ---------------- edge index access (int32 expected; int64 tolerated) ----
__global__ void k_detect(const int* __restrict__ ei32) {
    int z = 0;
    for (int i = 1; i < 128; i += 2) z |= ei32[i];
    g_is64 = (z == 0) ? 1 : 0;
}
__device__ __forceinline__ int edge_at(const void* ei, int idx) {
    int v;
    if (g_is64) v = (int)((const long long*)ei)[idx];
    else        v = ((const int*)ei)[idx];
    if ((unsigned)v >= NN) v = 0;
    return v;
}

// ---------------- graph preprocessing ----------------
__global__ void k_zero_pre() {
    int i = blockIdx.x * blockDim.x + threadIdx.x;
    if (i < NN) { g_deg[i] = 0.f; g_cnt[i] = 0; g_fill[i] = 0; }
}
__global__ void k_zero_stats() {
    int i = blockIdx.x * blockDim.x + threadIdx.x;
    if (i < HID) { g_sums[i] = 0.f; g_sq[i] = 0.f; }
}
__global__ void k_deg(const void* __restrict__ ei, const float* __restrict__ w) {
    int e = blockIdx.x * blockDim.x + threadIdx.x;
    if (e >= EE) return;
    int d = edge_at(ei, EE + e);
    atomicAdd(&g_deg[d], w[e]);
    atomicAdd(&g_cnt[d], 1);
}
__global__ void k_norm() {
    int i = blockIdx.x * blockDim.x + threadIdx.x;
    if (i >= NN) return;
    float dg = g_deg[i];
    g_dinv[i] = dg > 0.f ? rsqrtf(dg) : 0.f;
    int c = g_cnt[i];
    g_cntinv[i] = c > 0 ? 1.f / (float)c : 0.f;
}
__global__ void k_scan() {
    __shared__ int sh[1024];
    __shared__ int carry;
    int tid = threadIdx.x;
    if (tid == 0) carry = 0;
    __syncthreads();
    for (int base = 0; base < NN; base += 1024) {
        int idx = base + tid;
        int v = (idx < NN) ? g_cnt[idx] : 0;
        sh[tid] = v;
        __syncthreads();
        for (int off = 1; off < 1024; off <<= 1) {
            int t = (tid >= off) ? sh[tid - off] : 0;
            __syncthreads();
            sh[tid] += t;
            __syncthreads();
        }
        int c0 = carry;
        if (idx < NN) g_rowptr[idx] = c0 + sh[tid] - v;
        __syncthreads();
        if (tid == 0) carry = c0 + sh[1023];
        __syncthreads();
    }
    if (tid == 0) g_rowptr[NN] = carry;
}
__global__ void k_fill(const void* __restrict__ ei, const float* __restrict__ w) {
    int e = blockIdx.x * blockDim.x + threadIdx.x;
    if (e >= EE) return;
    int s = edge_at(ei, e);
    int d = edge_at(ei, EE + e);
    int pos = g_rowptr[d] + atomicAdd(&g_fill[d], 1);
    if (pos < EE) {
        g_col[pos] = s;
        g_ew[pos]  = g_dinv[s] * w[e] * g_dinv[d] * g_cntinv[d];
    }
}

// ---------------- propagation (gather SpMM over CSR) ----------------
template <int INSEL, int OUTSEL>
__global__ void k_spmm(int inoff, int ldin, int outoff, int ldout, int d, int shift) {
    const float* hin = bufsel<INSEL>() + inoff;
    float* hout = bufsel<OUTSEL>() + outoff;
    long long t = (long long)blockIdx.x * blockDim.x + threadIdx.x;
    long long total = (long long)NN * d;
    if (t >= total) return;
    int i = (int)(t >> shift);
    int f = (int)(t & (d - 1));
    int s = g_rowptr[i], e = g_rowptr[i + 1];
    float acc = 0.f;
    for (int j = s; j < e; j++)
        acc += g_ew[j] * __ldg(&hin[(size_t)g_col[j] * ldin + f]);
    hout[(size_t)i * ldout + f] = acc;
}

__global__ void k_copy_x(const float* __restrict__ x) {
    int t = blockIdx.x * blockDim.x + threadIdx.x;
    if (t >= NN * FIN) return;
    int n = t >> 7, f = t & 127;
    g_Xcat[(size_t)n * 512 + f] = x[t];
}

// ---------------- tensor-core GEMM (bf16 3-term split, fp32 accuracy) ----
// C[M,1024] = A[M,Kd] @ B[Kd,1024], block tile 128x64x32, 8 warps
#define BM 128
#define BN 64
#define BK 32
#define ALD (BK + 8)
#define BLD (BN + 8)
#define SLD 20   // staging stride: MUST be multiple of 4 for fp32 wmma store

__device__ __forceinline__ void split_bf16(float v, __nv_bfloat16& h, __nv_bfloat16& l) {
    h = __float2bfloat16(v);
    l = __float2bfloat16(v - __bfloat162float(h));
}

template <int ASEL, int CSEL>
__global__ __launch_bounds__(256)
void k_gemm_tc(int lda, const float* __restrict__ B, int ldb,
               int ldc, int M, int Kd) {
    const float* A = bufsel<ASEL>();
    float* C = bufsel<CSEL>();

    __shared__ __nv_bfloat16 Ahi[BM][ALD];
    __shared__ __nv_bfloat16 Alo[BM][ALD];
    __shared__ __nv_bfloat16 Bhi[BK][BLD];
    __shared__ __nv_bfloat16 Blo[BK][BLD];
    __shared__ float stage[8][16][SLD];

    const int tid  = threadIdx.x;
    const int lane = tid & 31;
    const int wid  = tid >> 5;
    const int wm   = wid >> 1;     // 0..3  (32-row strip)
    const int wn   = wid & 1;      // 0..1  (32-col strip)
    const int row0 = blockIdx.y * BM;
    const int col0 = blockIdx.x * BN;
    const bool full = (row0 + BM <= M);

    wmma::fragment<wmma::accumulator, 16, 16, 16, float> acc[2][2];
#pragma unroll
    for (int i = 0; i < 2; i++)
#pragma unroll
        for (int j = 0; j < 2; j++) wmma::fill_fragment(acc[i][j], 0.f);

    for (int kk = 0; kk < Kd; kk += BK) {
        // A tile: 128x32 fp32 = 1024 float4 slots, 256 thr x 4
#pragma unroll
        for (int s = 0; s < 4; s++) {
            int i4 = tid + s * 256;
            int r = i4 >> 3;
            int c = (i4 & 7) * 4;
            float4 v = make_float4(0.f, 0.f, 0.f, 0.f);
            if (row0 + r < M)
                v = *reinterpret_cast<const float4*>(&A[(size_t)(row0 + r) * lda + kk + c]);
            split_bf16(v.x, Ahi[r][c + 0], Alo[r][c + 0]);
            split_bf16(v.y, Ahi[r][c + 1], Alo[r][c + 1]);
            split_bf16(v.z, Ahi[r][c + 2], Alo[r][c + 2]);
            split_bf16(v.w, Ahi[r][c + 3], Alo[r][c + 3]);
        }
        // B tile: 32x64 fp32 = 512 float4 slots, 256 thr x 2
#pragma unroll
        for (int s = 0; s < 2; s++) {
            int i4 = tid + s * 256;
            int r = i4 >> 4;
            int c = (i4 & 15) * 4;
            float4 v = *reinterpret_cast<const float4*>(&B[(size_t)(kk + r) * ldb + col0 + c]);
            split_bf16(v.x, Bhi[r][c + 0], Blo[r][c + 0]);
            split_bf16(v.y, Bhi[r][c + 1], Blo[r][c + 1]);
            split_bf16(v.z, Bhi[r][c + 2], Blo[r][c + 2]);
            split_bf16(v.w, Bhi[r][c + 3], Blo[r][c + 3]);
        }
        __syncthreads();

#pragma unroll
        for (int ks = 0; ks < BK; ks += 16) {
            wmma::fragment<wmma::matrix_a, 16, 16, 16, __nv_bfloat16, wmma::row_major> ah[2], al[2];
            wmma::fragment<wmma::matrix_b, 16, 16, 16, __nv_bfloat16, wmma::row_major> bh[2], bl[2];
#pragma unroll
            for (int i = 0; i < 2; i++) {
                int mr = wm * 32 + i * 16;
                wmma::load_matrix_sync(ah[i], &Ahi[mr][ks], ALD);
                wmma::load_matrix_sync(al[i], &Alo[mr][ks], ALD);
            }
#pragma unroll
            for (int j = 0; j < 2; j++) {
                int nc = wn * 32 + j * 16;
                wmma::load_matrix_sync(bh[j], &Bhi[ks][nc], BLD);
                wmma::load_matrix_sync(bl[j], &Blo[ks][nc], BLD);
            }
#pragma unroll
            for (int i = 0; i < 2; i++)
#pragma unroll
                for (int j = 0; j < 2; j++) {
                    wmma::mma_sync(acc[i][j], ah[i], bh[j], acc[i][j]);
                    wmma::mma_sync(acc[i][j], ah[i], bl[j], acc[i][j]);
                    wmma::mma_sync(acc[i][j], al[i], bh[j], acc[i][j]);
                }
        }
        __syncthreads();
    }

    // epilogue: direct store for full tiles; staging only for the ragged tail
#pragma unroll
    for (int i = 0; i < 2; i++)
#pragma unroll
        for (int j = 0; j < 2; j++) {
            int r0 = row0 + wm * 32 + i * 16;
            int c0 = col0 + wn * 32 + j * 16;
            if (full) {
                wmma::store_matrix_sync(&C[(size_t)r0 * ldc + c0], acc[i][j], ldc,
                                        wmma::mem_row_major);
            } else {
                wmma::store_matrix_sync(&stage[wid][0][0], acc[i][j], SLD,
                                        wmma::mem_row_major);
                __syncwarp();
#pragma unroll
                for (int e = 0; e < 8; e++) {
                    int idx = lane + e * 32;
                    int rr = idx >> 4, cc = idx & 15;
                    if (r0 + rr < M)
                        C[(size_t)(r0 + rr) * ldc + c0 + cc] = stage[wid][rr][cc];
                }
                __syncwarp();
            }
        }
}

// bias + ELU (fp32, separate cheap pass)
template <int CSEL>
__global__ void k_biaselu(const float* __restrict__ bias) {
    float* C = bufsel<CSEL>();
    long long t = (long long)blockIdx.x * blockDim.x + threadIdx.x;
    if (t * 4 >= (long long)NN * HID) return;
    float4 v = *reinterpret_cast<float4*>(&C[t * 4]);
    int c = (int)((t * 4) & (HID - 1));
    v.x += bias[c + 0];
    v.y += bias[c + 1];
    v.z += bias[c + 2];
    v.w += bias[c + 3];
    v.x = v.x > 0.f ? v.x : expm1f(v.x);
    v.y = v.y > 0.f ? v.y : expm1f(v.y);
    v.z = v.z > 0.f ? v.z : expm1f(v.z);
    v.w = v.w > 0.f ? v.w : expm1f(v.w);
    *reinterpret_cast<float4*>(&C[t * 4]) = v;
}

// ---------------- GraphNorm ----------------
#define RPB 512
template <int XSEL>
__global__ void k_colsum(int ld) {
    const float* X = bufsel<XSEL>();
    int c  = blockIdx.x * blockDim.x + threadIdx.x;
    int r0 = blockIdx.y * RPB;
    int r1 = min(r0 + RPB, NN);
    float acc = 0.f;
    for (int r = r0; r < r1; r++) acc += X[(size_t)r * ld + c];
    atomicAdd(&g_sums[c], acc);
}
template <int XSEL, int YSEL>
__global__ void k_center(int ldx, int yoff, int ldy, const float* __restrict__ a) {
    const float* X = bufsel<XSEL>();
    float* Y = bufsel<YSEL>() + yoff;
    int c  = blockIdx.x * blockDim.x + threadIdx.x;
    int r0 = blockIdx.y * RPB;
    int r1 = min(r0 + RPB, NN);
    float am = a[c] * (g_sums[c] * (1.f / NN));
    float acc = 0.f;
    for (int r = r0; r < r1; r++) {
        float y = X[(size_t)r * ldx + c] - am;
        Y[(size_t)r * ldy + c] = y;
        acc += y * y;
    }
    atomicAdd(&g_sq[c], acc);
}
template <int YSEL>
__global__ void k_gnfinal(int yoff, int ld,
                          const float* __restrict__ g, const float* __restrict__ be) {
    float* Y = bufsel<YSEL>() + yoff;
    long long t = (long long)blockIdx.x * blockDim.x + threadIdx.x;
    if (t >= (long long)NN * HID) return;
    int c = (int)(t & (HID - 1));
    size_t idx = (size_t)(t >> 10) * ld + c;
    float s = g[c] * rsqrtf(g_sq[c] * (1.f / NN) + EPSV);
    Y[idx] = Y[idx] * s + be[c];
}

// ---------------- layer 3: project then Horner-propagate ----------------
__global__ void k_zproj(const float* __restrict__ W3) {
    int t = blockIdx.x * blockDim.x + threadIdx.x;
    if (t >= NN * 64) return;
    int n = t >> 6, o = t & 63;
    int k = o >> 4, c = o & 15;
    const float* hr = g_T1 + (size_t)n * HID;
    const float* wp = W3 + (size_t)k * HID * CLS + c;
    float acc = 0.f;
#pragma unroll 8
    for (int i = 0; i < HID; i++)
        acc += hr[i] * __ldg(&wp[(size_t)i * CLS]);
    g_Z[(size_t)n * 64 + o] = acc;
}
template <int USEL>
__global__ void k_add16(int zoff) {
    float* U = bufsel<USEL>();
    int t = blockIdx.x * blockDim.x + threadIdx.x;
    if (t >= NN * CLS) return;
    int n = t >> 4, c = t & 15;
    U[t] += g_Z[(size_t)n * 64 + zoff + c];
}
__global__ void k_final(float* __restrict__ out, const float* __restrict__ b3) {
    int t = blockIdx.x * blockDim.x + threadIdx.x;
    if (t >= NN * CLS) return;
    int n = t >> 4, c = t & 15;
    out[t] = g_U[t] + g_Z[(size_t)n * 64 + c] + b3[c];
}

// ---------------- host launcher ----------------
extern "C" void kernel_launch(void* const* d_in, const int* in_sizes, int n_in,
                              void* d_out, int out_size) {
    const float* x   = (const float*)d_in[0];
    const void*  ei  = d_in[1];
    const float* w   = (const float*)d_in[2];
    const float* W1  = (const float*)d_in[3];
    const float* b1  = (const float*)d_in[4];
    const float* g1  = (const float*)d_in[5];
    const float* be1 = (const float*)d_in[6];
    const float* a1  = (const float*)d_in[7];
    const float* W2  = (const float*)d_in[8];
    const float* b2  = (const float*)d_in[9];
    const float* g2  = (const float*)d_in[10];
    const float* be2 = (const float*)d_in[11];
    const float* a2  = (const float*)d_in[12];
    const float* W3  = (const float*)d_in[13];
    const float* b3  = (const float*)d_in[14];
    float* out = (float*)d_out;

    const int TB = 256;
    // --- graph preprocessing ---
    k_detect<<<1, 1>>>((const int*)ei);
    k_zero_pre<<<(NN + TB - 1) / TB, TB>>>();
    k_deg<<<(EE + TB - 1) / TB, TB>>>(ei, w);
    k_norm<<<(NN + TB - 1) / TB, TB>>>();
    k_scan<<<1, 1024>>>();
    k_fill<<<(EE + TB - 1) / TB, TB>>>(ei, w);

    // --- layer 1: hop-concat (d=128), TC GEMM [N,512]@[512,1024] ---
    k_copy_x<<<(NN * FIN + TB - 1) / TB, TB>>>(x);
    for (int k = 1; k <= 3; k++)
        k_spmm<B_XCAT, B_XCAT><<<(int)(((long long)NN * 128 + TB - 1) / TB), TB>>>(
            (k - 1) * 128, 512, k * 128, 512, 128, 7);
    k_gemm_tc<B_XCAT, B_T1><<<dim3(HID / BN, (NN + BM - 1) / BM), 256>>>(
        512, W1, HID, HID, NN, 512);
    k_biaselu<B_T1><<<(int)(((long long)NN * HID / 4 + TB - 1) / TB), TB>>>(b1);

    // --- GraphNorm 1 -> Hcat slice 0 ---
    k_zero_stats<<<(HID + TB - 1) / TB, TB>>>();
    k_colsum<B_T1><<<dim3(HID / TB, (NN + RPB - 1) / RPB), TB>>>(HID);
    k_center<B_T1, B_HCAT><<<dim3(HID / TB, (NN + RPB - 1) / RPB), TB>>>(HID, 0, 4096, a1);
    k_gnfinal<B_HCAT><<<(int)(((long long)NN * HID + TB - 1) / TB), TB>>>(0, 4096, g1, be1);

    // --- layer 2: hop-concat (d=1024), TC GEMM [N,4096]@[4096,1024] ---
    for (int k = 1; k <= 3; k++)
        k_spmm<B_HCAT, B_HCAT><<<(int)(((long long)NN * 1024 + TB - 1) / TB), TB>>>(
            (k - 1) * 1024, 4096, k * 1024, 4096, 1024, 10);
    k_gemm_tc<B_HCAT, B_T2><<<dim3(HID / BN, (NN + BM - 1) / BM), 256>>>(
        4096, W2, HID, HID, NN, 4096);
    k_biaselu<B_T2><<<(int)(((long long)NN * HID / 4 + TB - 1) / TB), TB>>>(b2);

    // --- GraphNorm 2 -> T1 (h2) ---
    k_zero_stats<<<(HID + TB - 1) / TB, TB>>>();
    k_colsum<B_T2><<<dim3(HID / TB, (NN + RPB - 1) / RPB), TB>>>(HID);
    k_center<B_T2, B_T1><<<dim3(HID / TB, (NN + RPB - 1) / RPB), TB>>>(HID, 0, HID, a2);
    k_gnfinal<B_T1><<<(int)(((long long)NN * HID + TB - 1) / TB), TB>>>(0, HID, g2, be2);

    // --- layer 3: project first, then Horner over A ---
    k_zproj<<<(NN * 64 + TB - 1) / TB, TB>>>(W3);
    k_spmm<B_Z, B_U><<<(NN * CLS + TB - 1) / TB, TB>>>(48, 64, 0, 16, 16, 4);  // U = A z3
    k_add16<B_U><<<(NN * CLS + TB - 1) / TB, TB>>>(32);                        // U += z2
    k_spmm<B_U, B_V><<<(NN * CLS + TB - 1) / TB, TB>>>(0, 16, 0, 16, 16, 4);   // V = A U
    k_add16<B_V><<<(NN * CLS + TB - 1) / TB, TB>>>(16);                        // V += z1
    k_spmm<B_V, B_U><<<(NN * CLS + TB - 1) / TB, TB>>>(0, 16, 0, 16, 16, 4);   // U = A V
    k_final<<<(NN * CLS + TB - 1) / TB, TB>>>(out, b3);                        // out = U + z0 + b3
}

// round 10
// speedup vs baseline: 1.3905x; 1.0913x over previous
#include <cuda_runtime.h>
#include <cuda_bf16.h>
#include <mma.h>
#include <math.h>

using namespace nvcuda;

#define NN   50000
#define EE   200000
#define FIN  128
#define HID  1024
#define CLS  16
#define EPSV 1e-5f

// ---------------- scratch (static __device__, no allocs) ----------------
// NOTE: total static __device__ size MUST stay < 2^31 bytes (cubin reloc limit).
// Current total ~1.98 GB.
__device__ float g_deg[NN];
__device__ int   g_cnt[NN];
__device__ float g_dinv[NN];
__device__ float g_cntinv[NN];
__device__ int   g_rowptr[NN + 1];
__device__ int   g_fill[NN];
__device__ int   g_col[EE];
__device__ float g_ew[EE];
__device__ int   g_is64;

__device__ __align__(16) float g_Xcat[(size_t)NN * 512];   // [N, 4*128]
__device__ __align__(16) float g_T1[(size_t)NN * HID];     // GEMM out / h2 (in-place GN2)
__device__ __align__(16) float g_Hcat[(size_t)NN * 4096];  // [N, 4*1024]
__device__ __align__(16) float g_Z[(size_t)NN * 64];       // [N, 4*16]
__device__ __align__(16) float g_U[(size_t)NN * CLS];
__device__ __align__(16) float g_V[(size_t)NN * CLS];
__device__ float g_sums[HID];
__device__ float g_sq[HID];

// bf16 hi/lo split buffers (A: activations, B: weights)
__device__ __align__(16) __nv_bfloat16 g_Ahi[(size_t)NN * 4096];
__device__ __align__(16) __nv_bfloat16 g_Alo[(size_t)NN * 4096];
__device__ __align__(16) __nv_bfloat16 g_Bhi[(size_t)4096 * 1024];
__device__ __align__(16) __nv_bfloat16 g_Blo[(size_t)4096 * 1024];

// compile-time buffer selectors
#define B_XCAT 0
#define B_T1   1
#define B_HCAT 3
#define B_Z    4
#define B_U    5
#define B_V    6
template <int S> __device__ __forceinline__ float* bufsel() {
    if (S == B_XCAT) return g_Xcat;
    if (S == B_T1)   return g_T1;
    if (S == B_HCAT) return g_Hcat;
    if (S == B_Z)    return g_Z;
    if (S == B_U)    return g_U;
    return g_V;
}

// ---------------- edge index access (int32 expected; int64 tolerated) ----
__global__ void k_detect(const int* __restrict__ ei32) {
    int z = 0;
    for (int i = 1; i < 128; i += 2) z |= ei32[i];
    g_is64 = (z == 0) ? 1 : 0;
}
__device__ __forceinline__ int edge_at(const void* ei, int idx) {
    int v;
    if (g_is64) v = (int)((const long long*)ei)[idx];
    else        v = ((const int*)ei)[idx];
    if ((unsigned)v >= NN) v = 0;
    return v;
}

// ---------------- graph preprocessing ----------------
__global__ void k_zero_pre() {
    int i = blockIdx.x * blockDim.x + threadIdx.x;
    if (i < NN) { g_deg[i] = 0.f; g_cnt[i] = 0; g_fill[i] = 0; }
}
__global__ void k_zero_stats() {
    int i = blockIdx.x * blockDim.x + threadIdx.x;
    if (i < HID) { g_sums[i] = 0.f; g_sq[i] = 0.f; }
}
__global__ void k_deg(const void* __restrict__ ei, const float* __restrict__ w) {
    int e = blockIdx.x * blockDim.x + threadIdx.x;
    if (e >= EE) return;
    int d = edge_at(ei, EE + e);
    atomicAdd(&g_deg[d], w[e]);
    atomicAdd(&g_cnt[d], 1);
}
__global__ void k_norm() {
    int i = blockIdx.x * blockDim.x + threadIdx.x;
    if (i >= NN) return;
    float dg = g_deg[i];
    g_dinv[i] = dg > 0.f ? rsqrtf(dg) : 0.f;
    int c = g_cnt[i];
    g_cntinv[i] = c > 0 ? 1.f / (float)c : 0.f;
}
__global__ void k_scan() {
    __shared__ int sh[1024];
    __shared__ int carry;
    int tid = threadIdx.x;
    if (tid == 0) carry = 0;
    __syncthreads();
    for (int base = 0; base < NN; base += 1024) {
        int idx = base + tid;
        int v = (idx < NN) ? g_cnt[idx] : 0;
        sh[tid] = v;
        __syncthreads();
        for (int off = 1; off < 1024; off <<= 1) {
            int t = (tid >= off) ? sh[tid - off] : 0;
            __syncthreads();
            sh[tid] += t;
            __syncthreads();
        }
        int c0 = carry;
        if (idx < NN) g_rowptr[idx] = c0 + sh[tid] - v;
        __syncthreads();
        if (tid == 0) carry = c0 + sh[1023];
        __syncthreads();
    }
    if (tid == 0) g_rowptr[NN] = carry;
}
__global__ void k_fill(const void* __restrict__ ei, const float* __restrict__ w) {
    int e = blockIdx.x * blockDim.x + threadIdx.x;
    if (e >= EE) return;
    int s = edge_at(ei, e);
    int d = edge_at(ei, EE + e);
    int pos = g_rowptr[d] + atomicAdd(&g_fill[d], 1);
    if (pos < EE) {
        g_col[pos] = s;
        g_ew[pos]  = g_dinv[s] * w[e] * g_dinv[d] * g_cntinv[d];
    }
}

// ---------------- propagation (gather SpMM over CSR) ----------------
template <int INSEL, int OUTSEL>
__global__ void k_spmm(int inoff, int ldin, int outoff, int ldout, int d, int shift) {
    const float* hin = bufsel<INSEL>() + inoff;
    float* hout = bufsel<OUTSEL>() + outoff;
    long long t = (long long)blockIdx.x * blockDim.x + threadIdx.x;
    long long total = (long long)NN * d;
    if (t >= total) return;
    int i = (int)(t >> shift);
    int f = (int)(t & (d - 1));
    int s = g_rowptr[i], e = g_rowptr[i + 1];
    float acc = 0.f;
    for (int j = s; j < e; j++)
        acc += g_ew[j] * __ldg(&hin[(size_t)g_col[j] * ldin + f]);
    hout[(size_t)i * ldout + f] = acc;
}

__global__ void k_copy_x(const float* __restrict__ x) {
    int t = blockIdx.x * blockDim.x + threadIdx.x;
    if (t >= NN * FIN) return;
    int n = t >> 7, f = t & 127;
    g_Xcat[(size_t)n * 512 + f] = x[t];
}

// ---------------- fp32 -> bf16 hi/lo split (streaming) -------------------
__device__ __forceinline__ void split_store(const float* __restrict__ src,
                                            __nv_bfloat16* __restrict__ hi,
                                            __nv_bfloat16* __restrict__ lo,
                                            long long n) {
    long long t = (long long)blockIdx.x * blockDim.x + threadIdx.x;
    if (t * 4 >= n) return;
    float4 v = *reinterpret_cast<const float4*>(&src[t * 4]);
    __nv_bfloat16 hx = __float2bfloat16(v.x);
    __nv_bfloat16 hy = __float2bfloat16(v.y);
    __nv_bfloat16 hz = __float2bfloat16(v.z);
    __nv_bfloat16 hw = __float2bfloat16(v.w);
    __nv_bfloat162 h01, h23, l01, l23;
    h01.x = hx; h01.y = hy; h23.x = hz; h23.y = hw;
    l01.x = __float2bfloat16(v.x - __bfloat162float(hx));
    l01.y = __float2bfloat16(v.y - __bfloat162float(hy));
    l23.x = __float2bfloat16(v.z - __bfloat162float(hz));
    l23.y = __float2bfloat16(v.w - __bfloat162float(hw));
    *reinterpret_cast<__nv_bfloat162*>(&hi[t * 4])     = h01;
    *reinterpret_cast<__nv_bfloat162*>(&hi[t * 4 + 2]) = h23;
    *reinterpret_cast<__nv_bfloat162*>(&lo[t * 4])     = l01;
    *reinterpret_cast<__nv_bfloat162*>(&lo[t * 4 + 2]) = l23;
}
template <int INSEL>
__global__ void k_split_a(long long n) {      // internal buffer -> A hi/lo
    split_store(bufsel<INSEL>(), g_Ahi, g_Alo, n);
}
__global__ void k_split_b(const float* __restrict__ W, long long n) {  // weights -> B hi/lo
    split_store(W, g_Bhi, g_Blo, n);
}

// ---------------- tensor-core GEMM (pre-split bf16, 3-term, fused epi) ---
// C[M,1024] = A[M,Kd] @ B[Kd,1024]; block 128x128x32, 8 warps, warp 32x64
#define BM 128
#define BN 128
#define BK 32
#define ALD 40    // bf16 row stride for A smem (mult of 8)
#define BLD 136   // bf16 row stride for B smem (mult of 8)
#define SLD 20    // fp32 staging stride (mult of 4)

template <int CSEL>
__global__ __launch_bounds__(256)
void k_gemm_tc(int Kd, int M, const float* __restrict__ bias, int do_elu) {
    const __nv_bfloat16* __restrict__ Ahi = g_Ahi;
    const __nv_bfloat16* __restrict__ Alo = g_Alo;
    const __nv_bfloat16* __restrict__ Bhi = g_Bhi;
    const __nv_bfloat16* __restrict__ Blo = g_Blo;
    float* C = bufsel<CSEL>();

    __shared__ __nv_bfloat16 Ash[BM][ALD];
    __shared__ __nv_bfloat16 Asl[BM][ALD];
    __shared__ __nv_bfloat16 Bsh[BK][BLD];
    __shared__ __nv_bfloat16 Bsl[BK][BLD];
    __shared__ float stage[8][16][SLD];

    const int tid  = threadIdx.x;
    const int lane = tid & 31;
    const int wid  = tid >> 5;
    const int wm   = wid >> 1;     // 0..3  (32-row strip)
    const int wn   = wid & 1;      // 0..1  (64-col strip)
    const int row0 = blockIdx.y * BM;
    const int col0 = blockIdx.x * BN;

    wmma::fragment<wmma::accumulator, 16, 16, 16, float> acc[2][4];
#pragma unroll
    for (int i = 0; i < 2; i++)
#pragma unroll
        for (int j = 0; j < 4; j++) wmma::fill_fragment(acc[i][j], 0.f);

    for (int kk = 0; kk < Kd; kk += BK) {
        // A tiles: 128x32 bf16 hi+lo, 2 uint4 per thread each
#pragma unroll
        for (int s = 0; s < 2; s++) {
            int idx = tid + s * 256;      // 0..511
            int r = idx >> 2;             // 0..127
            int c = (idx & 3) * 8;        // 0,8,16,24
            uint4 vh = make_uint4(0, 0, 0, 0);
            uint4 vl = make_uint4(0, 0, 0, 0);
            if (row0 + r < M) {
                size_t off = (size_t)(row0 + r) * Kd + kk + c;
                vh = *reinterpret_cast<const uint4*>(&Ahi[off]);
                vl = *reinterpret_cast<const uint4*>(&Alo[off]);
            }
            *reinterpret_cast<uint4*>(&Ash[r][c]) = vh;
            *reinterpret_cast<uint4*>(&Asl[r][c]) = vl;
        }
        // B tiles: 32x128 bf16 hi+lo, 2 uint4 per thread each
#pragma unroll
        for (int s = 0; s < 2; s++) {
            int idx = tid + s * 256;      // 0..511
            int r = idx >> 4;             // 0..31
            int c = (idx & 15) * 8;       // 0..120
            size_t off = (size_t)(kk + r) * HID + col0 + c;
            *reinterpret_cast<uint4*>(&Bsh[r][c]) =
                *reinterpret_cast<const uint4*>(&Bhi[off]);
            *reinterpret_cast<uint4*>(&Bsl[r][c]) =
                *reinterpret_cast<const uint4*>(&Blo[off]);
        }
        __syncthreads();

#pragma unroll
        for (int ks = 0; ks < BK; ks += 16) {
            wmma::fragment<wmma::matrix_a, 16, 16, 16, __nv_bfloat16, wmma::row_major> ah[2], al[2];
            wmma::fragment<wmma::matrix_b, 16, 16, 16, __nv_bfloat16, wmma::row_major> bh[4], bl[4];
#pragma unroll
            for (int i = 0; i < 2; i++) {
                int mr = wm * 32 + i * 16;
                wmma::load_matrix_sync(ah[i], &Ash[mr][ks], ALD);
                wmma::load_matrix_sync(al[i], &Asl[mr][ks], ALD);
            }
#pragma unroll
            for (int j = 0; j < 4; j++) {
                int nc = wn * 64 + j * 16;
                wmma::load_matrix_sync(bh[j], &Bsh[ks][nc], BLD);
                wmma::load_matrix_sync(bl[j], &Bsl[ks][nc], BLD);
            }
#pragma unroll
            for (int i = 0; i < 2; i++)
#pragma unroll
                for (int j = 0; j < 4; j++) {
                    wmma::mma_sync(acc[i][j], ah[i], bh[j], acc[i][j]);
                    wmma::mma_sync(acc[i][j], ah[i], bl[j], acc[i][j]);
                    wmma::mma_sync(acc[i][j], al[i], bh[j], acc[i][j]);
                }
        }
        __syncthreads();
    }

    // epilogue: stage -> +bias -> ELU -> float4 store (handles ragged M)
#pragma unroll
    for (int i = 0; i < 2; i++)
#pragma unroll
        for (int j = 0; j < 4; j++) {
            wmma::store_matrix_sync(&stage[wid][0][0], acc[i][j], SLD,
                                    wmma::mem_row_major);
            __syncwarp();
            int r0 = row0 + wm * 32 + i * 16;
            int c0 = col0 + wn * 64 + j * 16;
#pragma unroll
            for (int s = 0; s < 2; s++) {
                int slot = lane + s * 32;      // 0..63
                int rr = slot >> 2;
                int cc = (slot & 3) * 4;
                if (r0 + rr < M) {
                    float4 v = *reinterpret_cast<float4*>(&stage[wid][rr][cc]);
                    v.x += bias[c0 + cc + 0];
                    v.y += bias[c0 + cc + 1];
                    v.z += bias[c0 + cc + 2];
                    v.w += bias[c0 + cc + 3];
                    if (do_elu) {
                        v.x = v.x > 0.f ? v.x : expm1f(v.x);
                        v.y = v.y > 0.f ? v.y : expm1f(v.y);
                        v.z = v.z > 0.f ? v.z : expm1f(v.z);
                        v.w = v.w > 0.f ? v.w : expm1f(v.w);
                    }
                    *reinterpret_cast<float4*>(&C[(size_t)(r0 + rr) * HID + c0 + cc]) = v;
                }
            }
            __syncwarp();
        }
}

// ---------------- GraphNorm ----------------
#define RPB 512
template <int XSEL>
__global__ void k_colsum(int ld) {
    const float* X = bufsel<XSEL>();
    int c  = blockIdx.x * blockDim.x + threadIdx.x;
    int r0 = blockIdx.y * RPB;
    int r1 = min(r0 + RPB, NN);
    float acc = 0.f;
    for (int r = r0; r < r1; r++) acc += X[(size_t)r * ld + c];
    atomicAdd(&g_sums[c], acc);
}
// elementwise read-then-write per address: safe when X and Y alias (in-place)
template <int XSEL, int YSEL>
__global__ void k_center(int ldx, int yoff, int ldy, const float* __restrict__ a) {
    const float* X = bufsel<XSEL>();
    float* Y = bufsel<YSEL>() + yoff;
    int c  = blockIdx.x * blockDim.x + threadIdx.x;
    int r0 = blockIdx.y * RPB;
    int r1 = min(r0 + RPB, NN);
    float am = a[c] * (g_sums[c] * (1.f / NN));
    float acc = 0.f;
    for (int r = r0; r < r1; r++) {
        float y = X[(size_t)r * ldx + c] - am;
        Y[(size_t)r * ldy + c] = y;
        acc += y * y;
    }
    atomicAdd(&g_sq[c], acc);
}
template <int YSEL>
__global__ void k_gnfinal(int yoff, int ld,
                          const float* __restrict__ g, const float* __restrict__ be) {
    float* Y = bufsel<YSEL>() + yoff;
    long long t = (long long)blockIdx.x * blockDim.x + threadIdx.x;
    if (t >= (long long)NN * HID) return;
    int c = (int)(t & (HID - 1));
    size_t idx = (size_t)(t >> 10) * ld + c;
    float s = g[c] * rsqrtf(g_sq[c] * (1.f / NN) + EPSV);
    Y[idx] = Y[idx] * s + be[c];
}

// ---------------- layer 3: project then Horner-propagate ----------------
__global__ void k_zproj(const float* __restrict__ W3) {
    int t = blockIdx.x * blockDim.x + threadIdx.x;
    if (t >= NN * 64) return;
    int n = t >> 6, o = t & 63;
    int k = o >> 4, c = o & 15;
    const float* hr = g_T1 + (size_t)n * HID;
    const float* wp = W3 + (size_t)k * HID * CLS + c;
    float acc = 0.f;
#pragma unroll 8
    for (int i = 0; i < HID; i++)
        acc += hr[i] * __ldg(&wp[(size_t)i * CLS]);
    g_Z[(size_t)n * 64 + o] = acc;
}
template <int USEL>
__global__ void k_add16(int zoff) {
    float* U = bufsel<USEL>();
    int t = blockIdx.x * blockDim.x + threadIdx.x;
    if (t >= NN * CLS) return;
    int n = t >> 4, c = t & 15;
    U[t] += g_Z[(size_t)n * 64 + zoff + c];
}
__global__ void k_final(float* __restrict__ out, const float* __restrict__ b3) {
    int t = blockIdx.x * blockDim.x + threadIdx.x;
    if (t >= NN * CLS) return;
    int n = t >> 4, c = t & 15;
    out[t] = g_U[t] + g_Z[(size_t)n * 64 + c] + b3[c];
}

// ---------------- host launcher ----------------
extern "C" void kernel_launch(void* const* d_in, const int* in_sizes, int n_in,
                              void* d_out, int out_size) {
    const float* x   = (const float*)d_in[0];
    const void*  ei  = d_in[1];
    const float* w   = (const float*)d_in[2];
    const float* W1  = (const float*)d_in[3];
    const float* b1  = (const float*)d_in[4];
    const float* g1  = (const float*)d_in[5];
    const float* be1 = (const float*)d_in[6];
    const float* a1  = (const float*)d_in[7];
    const float* W2  = (const float*)d_in[8];
    const float* b2  = (const float*)d_in[9];
    const float* g2  = (const float*)d_in[10];
    const float* be2 = (const float*)d_in[11];
    const float* a2  = (const float*)d_in[12];
    const float* W3  = (const float*)d_in[13];
    const float* b3  = (const float*)d_in[14];
    float* out = (float*)d_out;

    const int TB = 256;
    // --- graph preprocessing ---
    k_detect<<<1, 1>>>((const int*)ei);
    k_zero_pre<<<(NN + TB - 1) / TB, TB>>>();
    k_deg<<<(EE + TB - 1) / TB, TB>>>(ei, w);
    k_norm<<<(NN + TB - 1) / TB, TB>>>();
    k_scan<<<1, 1024>>>();
    k_fill<<<(EE + TB - 1) / TB, TB>>>(ei, w);

    // --- layer 1: hop-concat (d=128) -> split -> TC GEMM [N,512]@[512,1024]
    k_copy_x<<<(NN * FIN + TB - 1) / TB, TB>>>(x);
    for (int k = 1; k <= 3; k++)
        k_spmm<B_XCAT, B_XCAT><<<(int)(((long long)NN * 128 + TB - 1) / TB), TB>>>(
            (k - 1) * 128, 512, k * 128, 512, 128, 7);
    {
        long long nA = (long long)NN * 512;
        k_split_a<B_XCAT><<<(int)((nA / 4 + TB - 1) / TB), TB>>>(nA);
        long long nB = 512LL * 1024;
        k_split_b<<<(int)((nB / 4 + TB - 1) / TB), TB>>>(W1, nB);
    }
    k_gemm_tc<B_T1><<<dim3(HID / BN, (NN + BM - 1) / BM), 256>>>(512, NN, b1, 1);

    // --- GraphNorm 1: T1 -> Hcat slice 0 ---
    k_zero_stats<<<(HID + TB - 1) / TB, TB>>>();
    k_colsum<B_T1><<<dim3(HID / TB, (NN + RPB - 1) / RPB), TB>>>(HID);
    k_center<B_T1, B_HCAT><<<dim3(HID / TB, (NN + RPB - 1) / RPB), TB>>>(HID, 0, 4096, a1);
    k_gnfinal<B_HCAT><<<(int)(((long long)NN * HID + TB - 1) / TB), TB>>>(0, 4096, g1, be1);

    // --- layer 2: hop-concat (d=1024) -> split -> TC GEMM [N,4096]@[4096,1024]
    for (int k = 1; k <= 3; k++)
        k_spmm<B_HCAT, B_HCAT><<<(int)(((long long)NN * 1024 + TB - 1) / TB), TB>>>(
            (k - 1) * 1024, 4096, k * 1024, 4096, 1024, 10);
    {
        long long nA = (long long)NN * 4096;
        k_split_a<B_HCAT><<<(int)((nA / 4 + TB - 1) / TB), TB>>>(nA);
        long long nB = 4096LL * 1024;
        k_split_b<<<(int)((nB / 4 + TB - 1) / TB), TB>>>(W2, nB);
    }
    k_gemm_tc<B_T1><<<dim3(HID / BN, (NN + BM - 1) / BM), 256>>>(4096, NN, b2, 1);

    // --- GraphNorm 2: in-place on T1 (h2) ---
    k_zero_stats<<<(HID + TB - 1) / TB, TB>>>();
    k_colsum<B_T1><<<dim3(HID / TB, (NN + RPB - 1) / RPB), TB>>>(HID);
    k_center<B_T1, B_T1><<<dim3(HID / TB, (NN + RPB - 1) / RPB), TB>>>(HID, 0, HID, a2);
    k_gnfinal<B_T1><<<(int)(((long long)NN * HID + TB - 1) / TB), TB>>>(0, HID, g2, be2);

    // --- layer 3: project first, then Horner over A ---
    k_zproj<<<(NN * 64 + TB - 1) / TB, TB>>>(W3);
    k_spmm<B_Z, B_U><<<(NN * CLS + TB - 1) / TB, TB>>>(48, 64, 0, 16, 16, 4);  // U = A z3
    k_add16<B_U><<<(NN * CLS + TB - 1) / TB, TB>>>(32);                        // U += z2
    k_spmm<B_U, B_V><<<(NN * CLS + TB - 1) / TB, TB>>>(0, 16, 0, 16, 16, 4);   // V = A U
    k_add16<B_V><<<(NN * CLS + TB - 1) / TB, TB>>>(16);                        // V += z1
    k_spmm<B_V, B_U><<<(NN * CLS + TB - 1) / TB, TB>>>(0, 16, 0, 16, 16, 4);   // U = A V
    k_final<<<(NN * CLS + TB - 1) / TB, TB>>>(out, b3);                        // out = U + z0 + b3
}

// round 13
// speedup vs baseline: 1.5887x; 1.1426x over previous
#include <cuda_runtime.h>
#include <cuda_bf16.h>
#include <mma.h>
#include <math.h>
#include <cstdint>

using namespace nvcuda;

#define NN   50000
#define EE   200000
#define FIN  128
#define HID  1024
#define CLS  16
#define EPSV 1e-5f

// ---------------- scratch (static __device__, no allocs) ----------------
// NOTE: total static __device__ size MUST stay < 2^31 bytes (cubin reloc limit).
__device__ float g_deg[NN];
__device__ int   g_cnt[NN];
__device__ float g_dinv[NN];
__device__ float g_cntinv[NN];
__device__ int   g_rowptr[NN + 1];
__device__ int   g_fill[NN];
__device__ int   g_col[EE];
__device__ float g_ew[EE];
__device__ int   g_is64;

__device__ __align__(16) float g_Xcat[(size_t)NN * 512];   // [N, 4*128]
__device__ __align__(16) float g_T1[(size_t)NN * HID];     // GEMM out / h2 (in-place GN2)
__device__ __align__(16) float g_Hcat[(size_t)NN * 4096];  // [N, 4*1024]
__device__ __align__(16) float g_Z[(size_t)NN * 64];       // [N, 4*16]
__device__ __align__(16) float g_U[(size_t)NN * CLS];
__device__ __align__(16) float g_V[(size_t)NN * CLS];
__device__ float g_sums[HID];
__device__ float g_sq[HID];

// bf16 hi/lo split buffers (A: activations, B: weights)
__device__ __align__(16) __nv_bfloat16 g_Ahi[(size_t)NN * 4096];
__device__ __align__(16) __nv_bfloat16 g_Alo[(size_t)NN * 4096];
__device__ __align__(16) __nv_bfloat16 g_Bhi[(size_t)4096 * 1024];
__device__ __align__(16) __nv_bfloat16 g_Blo[(size_t)4096 * 1024];

// compile-time buffer selectors
#define B_XCAT 0
#define B_T1   1
#define B_HCAT 3
#define B_Z    4
#define B_U    5
#define B_V    6
template <int S> __device__ __forceinline__ float* bufsel() {
    if (S == B_XCAT) return g_Xcat;
    if (S == B_T1)   return g_T1;
    if (S == B_HCAT) return g_Hcat;
    if (S == B_Z)    return g_Z;
    if (S == B_U)    return g_U;
    return g_V;
}

// ---------------- edge index access (int32 expected; int64 tolerated) ----
__global__ void k_detect(const int* __restrict__ ei32) {
    int z = 0;
    for (int i = 1; i < 128; i += 2) z |= ei32[i];
    g_is64 = (z == 0) ? 1 : 0;
}
__device__ __forceinline__ int edge_at(const void* ei, int idx) {
    int v;
    if (g_is64) v = (int)((const long long*)ei)[idx];
    else        v = ((const int*)ei)[idx];
    if ((unsigned)v >= NN) v = 0;
    return v;
}

// ---------------- graph preprocessing ----------------
__global__ void k_zero_pre() {
    int i = blockIdx.x * blockDim.x + threadIdx.x;
    if (i < NN) { g_deg[i] = 0.f; g_cnt[i] = 0; g_fill[i] = 0; }
}
__global__ void k_zero_stats() {
    int i = blockIdx.x * blockDim.x + threadIdx.x;
    if (i < HID) { g_sums[i] = 0.f; g_sq[i] = 0.f; }
}
__global__ void k_deg(const void* __restrict__ ei, const float* __restrict__ w) {
    int e = blockIdx.x * blockDim.x + threadIdx.x;
    if (e >= EE) return;
    int d = edge_at(ei, EE + e);
    atomicAdd(&g_deg[d], w[e]);
    atomicAdd(&g_cnt[d], 1);
}
__global__ void k_norm() {
    int i = blockIdx.x * blockDim.x + threadIdx.x;
    if (i >= NN) return;
    float dg = g_deg[i];
    g_dinv[i] = dg > 0.f ? rsqrtf(dg) : 0.f;
    int c = g_cnt[i];
    g_cntinv[i] = c > 0 ? 1.f / (float)c : 0.f;
}
__global__ void k_scan() {
    __shared__ int sh[1024];
    __shared__ int carry;
    int tid = threadIdx.x;
    if (tid == 0) carry = 0;
    __syncthreads();
    for (int base = 0; base < NN; base += 1024) {
        int idx = base + tid;
        int v = (idx < NN) ? g_cnt[idx] : 0;
        sh[tid] = v;
        __syncthreads();
        for (int off = 1; off < 1024; off <<= 1) {
            int t = (tid >= off) ? sh[tid - off] : 0;
            __syncthreads();
            sh[tid] += t;
            __syncthreads();
        }
        int c0 = carry;
        if (idx < NN) g_rowptr[idx] = c0 + sh[tid] - v;
        __syncthreads();
        if (tid == 0) carry = c0 + sh[1023];
        __syncthreads();
    }
    if (tid == 0) g_rowptr[NN] = carry;
}
__global__ void k_fill(const void* __restrict__ ei, const float* __restrict__ w) {
    int e = blockIdx.x * blockDim.x + threadIdx.x;
    if (e >= EE) return;
    int s = edge_at(ei, e);
    int d = edge_at(ei, EE + e);
    int pos = g_rowptr[d] + atomicAdd(&g_fill[d], 1);
    if (pos < EE) {
        g_col[pos] = s;
        g_ew[pos]  = g_dinv[s] * w[e] * g_dinv[d] * g_cntinv[d];
    }
}

// ---------------- propagation (gather SpMM over CSR) ----------------
template <int INSEL, int OUTSEL>
__global__ void k_spmm(int inoff, int ldin, int outoff, int ldout, int d, int shift) {
    const float* hin = bufsel<INSEL>() + inoff;
    float* hout = bufsel<OUTSEL>() + outoff;
    long long t = (long long)blockIdx.x * blockDim.x + threadIdx.x;
    long long total = (long long)NN * d;
    if (t >= total) return;
    int i = (int)(t >> shift);
    int f = (int)(t & (d - 1));
    int s = g_rowptr[i], e = g_rowptr[i + 1];
    float acc = 0.f;
    for (int j = s; j < e; j++)
        acc += g_ew[j] * __ldg(&hin[(size_t)g_col[j] * ldin + f]);
    hout[(size_t)i * ldout + f] = acc;
}

__global__ void k_copy_x(const float* __restrict__ x) {
    int t = blockIdx.x * blockDim.x + threadIdx.x;
    if (t >= NN * FIN) return;
    int n = t >> 7, f = t & 127;
    g_Xcat[(size_t)n * 512 + f] = x[t];
}

// ---------------- fp32 -> bf16 hi/lo split (streaming) -------------------
__device__ __forceinline__ void split_store(const float* __restrict__ src,
                                            __nv_bfloat16* __restrict__ hi,
                                            __nv_bfloat16* __restrict__ lo,
                                            long long n) {
    long long t = (long long)blockIdx.x * blockDim.x + threadIdx.x;
    if (t * 4 >= n) return;
    float4 v = *reinterpret_cast<const float4*>(&src[t * 4]);
    __nv_bfloat16 hx = __float2bfloat16(v.x);
    __nv_bfloat16 hy = __float2bfloat16(v.y);
    __nv_bfloat16 hz = __float2bfloat16(v.z);
    __nv_bfloat16 hw = __float2bfloat16(v.w);
    __nv_bfloat162 h01, h23, l01, l23;
    h01.x = hx; h01.y = hy; h23.x = hz; h23.y = hw;
    l01.x = __float2bfloat16(v.x - __bfloat162float(hx));
    l01.y = __float2bfloat16(v.y - __bfloat162float(hy));
    l23.x = __float2bfloat16(v.z - __bfloat162float(hz));
    l23.y = __float2bfloat16(v.w - __bfloat162float(hw));
    *reinterpret_cast<__nv_bfloat162*>(&hi[t * 4])     = h01;
    *reinterpret_cast<__nv_bfloat162*>(&hi[t * 4 + 2]) = h23;
    *reinterpret_cast<__nv_bfloat162*>(&lo[t * 4])     = l01;
    *reinterpret_cast<__nv_bfloat162*>(&lo[t * 4 + 2]) = l23;
}
template <int INSEL>
__global__ void k_split_a(long long n) {      // internal buffer -> A hi/lo
    split_store(bufsel<INSEL>(), g_Ahi, g_Alo, n);
}
__global__ void k_split_b(const float* __restrict__ W, long long n) {  // weights -> B hi/lo
    split_store(W, g_Bhi, g_Blo, n);
}

// ---------------- tensor-core GEMM (cp.async 2-stage, static smem) -------
// C[M,1024] = A[M,Kd] @ B[Kd,1024]; block 128x128x16, 8 warps, warp 32x64
#define BM 128
#define BN 128
#define BK 16
#define ALD 24                       // bf16 row stride A smem
#define BLD 136                      // bf16 row stride B smem
#define SLD 20                       // fp32 staging stride (mult of 4)
#define A_TILE (BM * ALD)            // 3072 bf16
#define B_TILE (BK * BLD)            // 2176 bf16
#define STAGE_ELEMS (2 * A_TILE + 2 * B_TILE)   // 10496 bf16 = 20992 B
// total static smem: 2 stages = 41984 B < 48 KB

__device__ __forceinline__ void cpa16(const __nv_bfloat16* sdst,
                                      const __nv_bfloat16* gsrc, bool pred) {
    unsigned int d = (unsigned int)__cvta_generic_to_shared(sdst);
    int sz = pred ? 16 : 0;
    asm volatile("cp.async.cg.shared.global [%0], [%1], 16, %2;\n"
                 :: "r"(d), "l"(gsrc), "r"(sz));
}

template <int CSEL>
__global__ __launch_bounds__(256, 2)
void k_gemm_tc(int Kd, int M, const float* __restrict__ bias, int do_elu) {
    __shared__ __nv_bfloat16 smbuf[2 * STAGE_ELEMS];
    float* C = bufsel<CSEL>();

    const int tid  = threadIdx.x;
    const int lane = tid & 31;
    const int wid  = tid >> 5;
    const int wm   = wid >> 1;     // 0..3  (32-row strip)
    const int wn   = wid & 1;      // 0..1  (64-col strip)
    const int row0 = blockIdx.y * BM;
    const int col0 = blockIdx.x * BN;

    // per-thread load coordinates (fixed across iters)
    const int ar = tid >> 1;             // 0..127
    const int ac = (tid & 1) * 8;        // 0,8
    const int br = tid >> 4;             // 0..15
    const int bc = (tid & 15) * 8;       // 0..120
    const bool apred = (row0 + ar < M);

    wmma::fragment<wmma::accumulator, 16, 16, 16, float> acc[2][4];
#pragma unroll
    for (int i = 0; i < 2; i++)
#pragma unroll
        for (int j = 0; j < 4; j++) wmma::fill_fragment(acc[i][j], 0.f);

    const int niters = Kd / BK;

    // stage loader: 4 cp.async per thread (Ahi, Alo, Bhi, Blo)
    auto load_stage = [&](int st, int kk) {
        __nv_bfloat16* base = smbuf + st * STAGE_ELEMS;
        size_t aoff = (size_t)(row0 + ar) * Kd + kk + ac;
        cpa16(base + ar * ALD + ac,          apred ? &g_Ahi[aoff] : g_Ahi, apred);
        cpa16(base + A_TILE + ar * ALD + ac, apred ? &g_Alo[aoff] : g_Alo, apred);
        size_t boff = (size_t)(kk + br) * HID + col0 + bc;
        cpa16(base + 2 * A_TILE + br * BLD + bc,          &g_Bhi[boff], true);
        cpa16(base + 2 * A_TILE + B_TILE + br * BLD + bc, &g_Blo[boff], true);
        asm volatile("cp.async.commit_group;\n" ::);
    };

    load_stage(0, 0);

    for (int it = 0; it < niters; it++) {
        if (it + 1 < niters) {
            load_stage((it + 1) & 1, (it + 1) * BK);
            asm volatile("cp.async.wait_group 1;\n" ::);
        } else {
            asm volatile("cp.async.wait_group 0;\n" ::);
        }
        __syncthreads();

        const __nv_bfloat16* cAhi = smbuf + (it & 1) * STAGE_ELEMS;
        const __nv_bfloat16* cAlo = cAhi + A_TILE;
        const __nv_bfloat16* cBhi = cAhi + 2 * A_TILE;
        const __nv_bfloat16* cBlo = cBhi + B_TILE;

        wmma::fragment<wmma::matrix_a, 16, 16, 16, __nv_bfloat16, wmma::row_major> ah[2], al[2];
        wmma::fragment<wmma::matrix_b, 16, 16, 16, __nv_bfloat16, wmma::row_major> bh[4], bl[4];
#pragma unroll
        for (int i = 0; i < 2; i++) {
            int mr = wm * 32 + i * 16;
            wmma::load_matrix_sync(ah[i], cAhi + mr * ALD, ALD);
            wmma::load_matrix_sync(al[i], cAlo + mr * ALD, ALD);
        }
#pragma unroll
        for (int j = 0; j < 4; j++) {
            int nc = wn * 64 + j * 16;
            wmma::load_matrix_sync(bh[j], cBhi + nc, BLD);
            wmma::load_matrix_sync(bl[j], cBlo + nc, BLD);
        }
#pragma unroll
        for (int i = 0; i < 2; i++)
#pragma unroll
            for (int j = 0; j < 4; j++) {
                wmma::mma_sync(acc[i][j], ah[i], bh[j], acc[i][j]);
                wmma::mma_sync(acc[i][j], ah[i], bl[j], acc[i][j]);
                wmma::mma_sync(acc[i][j], al[i], bh[j], acc[i][j]);
            }
        __syncthreads();
    }

    // epilogue: alias pipeline smem as fp32 staging; +bias, ELU, float4 store
    float* stg = reinterpret_cast<float*>(smbuf) + wid * 16 * SLD;
#pragma unroll
    for (int i = 0; i < 2; i++)
#pragma unroll
        for (int j = 0; j < 4; j++) {
            wmma::store_matrix_sync(stg, acc[i][j], SLD, wmma::mem_row_major);
            __syncwarp();
            int r0 = row0 + wm * 32 + i * 16;
            int c0 = col0 + wn * 64 + j * 16;
#pragma unroll
            for (int s = 0; s < 2; s++) {
                int slot = lane + s * 32;      // 0..63
                int rr = slot >> 2;
                int cc = (slot & 3) * 4;
                if (r0 + rr < M) {
                    float4 v = *reinterpret_cast<float4*>(&stg[rr * SLD + cc]);
                    v.x += bias[c0 + cc + 0];
                    v.y += bias[c0 + cc + 1];
                    v.z += bias[c0 + cc + 2];
                    v.w += bias[c0 + cc + 3];
                    if (do_elu) {
                        v.x = v.x > 0.f ? v.x : expm1f(v.x);
                        v.y = v.y > 0.f ? v.y : expm1f(v.y);
                        v.z = v.z > 0.f ? v.z : expm1f(v.z);
                        v.w = v.w > 0.f ? v.w : expm1f(v.w);
                    }
                    *reinterpret_cast<float4*>(&C[(size_t)(r0 + rr) * HID + c0 + cc]) = v;
                }
            }
            __syncwarp();
        }
}

// ---------------- GraphNorm ----------------
#define RPB 512
template <int XSEL>
__global__ void k_colsum(int ld) {
    const float* X = bufsel<XSEL>();
    int c  = blockIdx.x * blockDim.x + threadIdx.x;
    int r0 = blockIdx.y * RPB;
    int r1 = min(r0 + RPB, NN);
    float acc = 0.f;
    for (int r = r0; r < r1; r++) acc += X[(size_t)r * ld + c];
    atomicAdd(&g_sums[c], acc);
}
// elementwise read-then-write per address: safe when X and Y alias (in-place)
template <int XSEL, int YSEL>
__global__ void k_center(int ldx, int yoff, int ldy, const float* __restrict__ a) {
    const float* X = bufsel<XSEL>();
    float* Y = bufsel<YSEL>() + yoff;
    int c  = blockIdx.x * blockDim.x + threadIdx.x;
    int r0 = blockIdx.y * RPB;
    int r1 = min(r0 + RPB, NN);
    float am = a[c] * (g_sums[c] * (1.f / NN));
    float acc = 0.f;
    for (int r = r0; r < r1; r++) {
        float y = X[(size_t)r * ldx + c] - am;
        Y[(size_t)r * ldy + c] = y;
        acc += y * y;
    }
    atomicAdd(&g_sq[c], acc);
}
template <int YSEL>
__global__ void k_gnfinal(int yoff, int ld,
                          const float* __restrict__ g, const float* __restrict__ be) {
    float* Y = bufsel<YSEL>() + yoff;
    long long t = (long long)blockIdx.x * blockDim.x + threadIdx.x;
    if (t >= (long long)NN * HID) return;
    int c = (int)(t & (HID - 1));
    size_t idx = (size_t)(t >> 10) * ld + c;
    float s = g[c] * rsqrtf(g_sq[c] * (1.f / NN) + EPSV);
    Y[idx] = Y[idx] * s + be[c];
}

// ---------------- layer 3: project then Horner-propagate ----------------
__global__ void k_zproj(const float* __restrict__ W3) {
    int t = blockIdx.x * blockDim.x + threadIdx.x;
    if (t >= NN * 64) return;
    int n = t >> 6, o = t & 63;
    int k = o >> 4, c = o & 15;
    const float* hr = g_T1 + (size_t)n * HID;
    const float* wp = W3 + (size_t)k * HID * CLS + c;
    float acc = 0.f;
#pragma unroll 8
    for (int i = 0; i < HID; i++)
        acc += hr[i] * __ldg(&wp[(size_t)i * CLS]);
    g_Z[(size_t)n * 64 + o] = acc;
}
template <int USEL>
__global__ void k_add16(int zoff) {
    float* U = bufsel<USEL>();
    int t = blockIdx.x * blockDim.x + threadIdx.x;
    if (t >= NN * CLS) return;
    int n = t >> 4, c = t & 15;
    U[t] += g_Z[(size_t)n * 64 + zoff + c];
}
__global__ void k_final(float* __restrict__ out, const float* __restrict__ b3) {
    int t = blockIdx.x * blockDim.x + threadIdx.x;
    if (t >= NN * CLS) return;
    int n = t >> 4, c = t & 15;
    out[t] = g_U[t] + g_Z[(size_t)n * 64 + c] + b3[c];
}

// ---------------- host launcher ----------------
extern "C" void kernel_launch(void* const* d_in, const int* in_sizes, int n_in,
                              void* d_out, int out_size) {
    const float* x   = (const float*)d_in[0];
    const void*  ei  = d_in[1];
    const float* w   = (const float*)d_in[2];
    const float* W1  = (const float*)d_in[3];
    const float* b1  = (const float*)d_in[4];
    const float* g1  = (const float*)d_in[5];
    const float* be1 = (const float*)d_in[6];
    const float* a1  = (const float*)d_in[7];
    const float* W2  = (const float*)d_in[8];
    const float* b2  = (const float*)d_in[9];
    const float* g2  = (const float*)d_in[10];
    const float* be2 = (const float*)d_in[11];
    const float* a2  = (const float*)d_in[12];
    const float* W3  = (const float*)d_in[13];
    const float* b3  = (const float*)d_in[14];
    float* out = (float*)d_out;

    const int TB = 256;
    // --- graph preprocessing ---
    k_detect<<<1, 1>>>((const int*)ei);
    k_zero_pre<<<(NN + TB - 1) / TB, TB>>>();
    k_deg<<<(EE + TB - 1) / TB, TB>>>(ei, w);
    k_norm<<<(NN + TB - 1) / TB, TB>>>();
    k_scan<<<1, 1024>>>();
    k_fill<<<(EE + TB - 1) / TB, TB>>>(ei, w);

    // --- layer 1: hop-concat (d=128) -> split -> TC GEMM [N,512]@[512,1024]
    k_copy_x<<<(NN * FIN + TB - 1) / TB, TB>>>(x);
    for (int k = 1; k <= 3; k++)
        k_spmm<B_XCAT, B_XCAT><<<(int)(((long long)NN * 128 + TB - 1) / TB), TB>>>(
            (k - 1) * 128, 512, k * 128, 512, 128, 7);
    {
        long long nA = (long long)NN * 512;
        k_split_a<B_XCAT><<<(int)((nA / 4 + TB - 1) / TB), TB>>>(nA);
        long long nB = 512LL * 1024;
        k_split_b<<<(int)((nB / 4 + TB - 1) / TB), TB>>>(W1, nB);
    }
    k_gemm_tc<B_T1><<<dim3(HID / BN, (NN + BM - 1) / BM), 256>>>(512, NN, b1, 1);

    // --- GraphNorm 1: T1 -> Hcat slice 0 ---
    k_zero_stats<<<(HID + TB - 1) / TB, TB>>>();
    k_colsum<B_T1><<<dim3(HID / TB, (NN + RPB - 1) / RPB), TB>>>(HID);
    k_center<B_T1, B_HCAT><<<dim3(HID / TB, (NN + RPB - 1) / RPB), TB>>>(HID, 0, 4096, a1);
    k_gnfinal<B_HCAT><<<(int)(((long long)NN * HID + TB - 1) / TB), TB>>>(0, 4096, g1, be1);

    // --- layer 2: hop-concat (d=1024) -> split -> TC GEMM [N,4096]@[4096,1024]
    for (int k = 1; k <= 3; k++)
        k_spmm<B_HCAT, B_HCAT><<<(int)(((long long)NN * 1024 + TB - 1) / TB), TB>>>(
            (k - 1) * 1024, 4096, k * 1024, 4096, 1024, 10);
    {
        long long nA = (long long)NN * 4096;
        k_split_a<B_HCAT><<<(int)((nA / 4 + TB - 1) / TB), TB>>>(nA);
        long long nB = 4096LL * 1024;
        k_split_b<<<(int)((nB / 4 + TB - 1) / TB), TB>>>(W2, nB);
    }
    k_gemm_tc<B_T1><<<dim3(HID / BN, (NN + BM - 1) / BM), 256>>>(4096, NN, b2, 1);

    // --- GraphNorm 2: in-place on T1 (h2) ---
    k_zero_stats<<<(HID + TB - 1) / TB, TB>>>();
    k_colsum<B_T1><<<dim3(HID / TB, (NN + RPB - 1) / RPB), TB>>>(HID);
    k_center<B_T1, B_T1><<<dim3(HID / TB, (NN + RPB - 1) / RPB), TB>>>(HID, 0, HID, a2);
    k_gnfinal<B_T1><<<(int)(((long long)NN * HID + TB - 1) / TB), TB>>>(0, HID, g2, be2);

    // --- layer 3: project first, then Horner over A ---
    k_zproj<<<(NN * 64 + TB - 1) / TB, TB>>>(W3);
    k_spmm<B_Z, B_U><<<(NN * CLS + TB - 1) / TB, TB>>>(48, 64, 0, 16, 16, 4);  // U = A z3
    k_add16<B_U><<<(NN * CLS + TB - 1) / TB, TB>>>(32);                        // U += z2
    k_spmm<B_U, B_V><<<(NN * CLS + TB - 1) / TB, TB>>>(0, 16, 0, 16, 16, 4);   // V = A U
    k_add16<B_V><<<(NN * CLS + TB - 1) / TB, TB>>>(16);                        // V += z1
    k_spmm<B_V, B_U><<<(NN * CLS + TB - 1) / TB, TB>>>(0, 16, 0, 16, 16, 4);   // U = A V
    k_final<<<(NN * CLS + TB - 1) / TB, TB>>>(out, b3);                        // out = U + z0 + b3
}

// round 14
// speedup vs baseline: 1.6410x; 1.0329x over previous
#include <cuda_runtime.h>
#include <cuda_bf16.h>
#include <mma.h>
#include <math.h>
#include <cstdint>

using namespace nvcuda;

#define NN   50000
#define EE   200000
#define FIN  128
#define HID  1024
#define CLS  16
#define EPSV 1e-5f

// ---------------- scratch (static __device__, no allocs) ----------------
// NOTE: total static __device__ size MUST stay < 2^31 bytes (cubin reloc limit).
__device__ float g_deg[NN];
__device__ int   g_cnt[NN];
__device__ float g_dinv[NN];
__device__ float g_cntinv[NN];
__device__ int   g_rowptr[NN + 1];
__device__ int   g_fill[NN];
__device__ int   g_col[EE];
__device__ float g_ew[EE];
__device__ int   g_is64;

__device__ __align__(16) float g_Xcat[(size_t)NN * 512];   // [N, 4*128]
__device__ __align__(16) float g_T1[(size_t)NN * HID];     // GEMM out / h2 (in-place GN2)
__device__ __align__(16) float g_Hcat[(size_t)NN * 4096];  // [N, 4*1024]
__device__ __align__(16) float g_Z[(size_t)NN * 64];       // [N, 4*16]
__device__ __align__(16) float g_U[(size_t)NN * CLS];
__device__ __align__(16) float g_V[(size_t)NN * CLS];
__device__ float g_sums[HID];
__device__ float g_sq[HID];

// bf16 hi/lo split buffers (A: activations, B: weights)
__device__ __align__(16) __nv_bfloat16 g_Ahi[(size_t)NN * 4096];
__device__ __align__(16) __nv_bfloat16 g_Alo[(size_t)NN * 4096];
__device__ __align__(16) __nv_bfloat16 g_Bhi[(size_t)4096 * 1024];
__device__ __align__(16) __nv_bfloat16 g_Blo[(size_t)4096 * 1024];

// compile-time buffer selectors
#define B_XCAT 0
#define B_T1   1
#define B_HCAT 3
#define B_Z    4
#define B_U    5
#define B_V    6
template <int S> __device__ __forceinline__ float* bufsel() {
    if (S == B_XCAT) return g_Xcat;
    if (S == B_T1)   return g_T1;
    if (S == B_HCAT) return g_Hcat;
    if (S == B_Z)    return g_Z;
    if (S == B_U)    return g_U;
    return g_V;
}

__device__ __forceinline__ void dual_bf16(float v, size_t idx) {
    __nv_bfloat16 h = __float2bfloat16(v);
    g_Ahi[idx] = h;
    g_Alo[idx] = __float2bfloat16(v - __bfloat162float(h));
}

// ---------------- edge index access (int32 expected; int64 tolerated) ----
__global__ void k_detect(const int* __restrict__ ei32) {
    int z = 0;
    for (int i = 1; i < 128; i += 2) z |= ei32[i];
    g_is64 = (z == 0) ? 1 : 0;
}
__device__ __forceinline__ int edge_at(const void* ei, int idx) {
    int v;
    if (g_is64) v = (int)((const long long*)ei)[idx];
    else        v = ((const int*)ei)[idx];
    if ((unsigned)v >= NN) v = 0;
    return v;
}

// ---------------- graph preprocessing ----------------
__global__ void k_zero_pre() {
    int i = blockIdx.x * blockDim.x + threadIdx.x;
    if (i < NN) { g_deg[i] = 0.f; g_cnt[i] = 0; g_fill[i] = 0; }
}
__global__ void k_zero_stats() {
    int i = blockIdx.x * blockDim.x + threadIdx.x;
    if (i < HID) { g_sums[i] = 0.f; g_sq[i] = 0.f; }
}
__global__ void k_deg(const void* __restrict__ ei, const float* __restrict__ w) {
    int e = blockIdx.x * blockDim.x + threadIdx.x;
    if (e >= EE) return;
    int d = edge_at(ei, EE + e);
    atomicAdd(&g_deg[d], w[e]);
    atomicAdd(&g_cnt[d], 1);
}
__global__ void k_norm() {
    int i = blockIdx.x * blockDim.x + threadIdx.x;
    if (i >= NN) return;
    float dg = g_deg[i];
    g_dinv[i] = dg > 0.f ? rsqrtf(dg) : 0.f;
    int c = g_cnt[i];
    g_cntinv[i] = c > 0 ? 1.f / (float)c : 0.f;
}
__global__ void k_scan() {
    __shared__ int sh[1024];
    __shared__ int carry;
    int tid = threadIdx.x;
    if (tid == 0) carry = 0;
    __syncthreads();
    for (int base = 0; base < NN; base += 1024) {
        int idx = base + tid;
        int v = (idx < NN) ? g_cnt[idx] : 0;
        sh[tid] = v;
        __syncthreads();
        for (int off = 1; off < 1024; off <<= 1) {
            int t = (tid >= off) ? sh[tid - off] : 0;
            __syncthreads();
            sh[tid] += t;
            __syncthreads();
        }
        int c0 = carry;
        if (idx < NN) g_rowptr[idx] = c0 + sh[tid] - v;
        __syncthreads();
        if (tid == 0) carry = c0 + sh[1023];
        __syncthreads();
    }
    if (tid == 0) g_rowptr[NN] = carry;
}
__global__ void k_fill(const void* __restrict__ ei, const float* __restrict__ w) {
    int e = blockIdx.x * blockDim.x + threadIdx.x;
    if (e >= EE) return;
    int s = edge_at(ei, e);
    int d = edge_at(ei, EE + e);
    int pos = g_rowptr[d] + atomicAdd(&g_fill[d], 1);
    if (pos < EE) {
        g_col[pos] = s;
        g_ew[pos]  = g_dinv[s] * w[e] * g_dinv[d] * g_cntinv[d];
    }
}

// ---------------- propagation (gather SpMM over CSR) ----------------
// DUAL=1: also emit bf16 hi/lo into g_Ahi/g_Alo at [i*ldA + aoff + f]
template <int INSEL, int OUTSEL, int DUAL>
__global__ void k_spmm(int inoff, int ldin, int outoff, int ldout, int d, int shift,
                       int aoff, int ldA) {
    const float* hin = bufsel<INSEL>() + inoff;
    float* hout = bufsel<OUTSEL>() + outoff;
    long long t = (long long)blockIdx.x * blockDim.x + threadIdx.x;
    long long total = (long long)NN * d;
    if (t >= total) return;
    int i = (int)(t >> shift);
    int f = (int)(t & (d - 1));
    int s = g_rowptr[i], e = g_rowptr[i + 1];
    float acc = 0.f;
    for (int j = s; j < e; j++)
        acc += g_ew[j] * __ldg(&hin[(size_t)g_col[j] * ldin + f]);
    hout[(size_t)i * ldout + f] = acc;
    if (DUAL) dual_bf16(acc, (size_t)i * ldA + aoff + f);
}

__global__ void k_copy_x(const float* __restrict__ x) {
    int t = blockIdx.x * blockDim.x + threadIdx.x;
    if (t >= NN * FIN) return;
    int n = t >> 7, f = t & 127;
    float v = x[t];
    g_Xcat[(size_t)n * 512 + f] = v;
    dual_bf16(v, (size_t)n * 512 + f);
}

// ---------------- fp32 -> bf16 hi/lo split (weights only) ----------------
__global__ void k_split_b(const float* __restrict__ W, long long n) {
    long long t = (long long)blockIdx.x * blockDim.x + threadIdx.x;
    if (t * 4 >= n) return;
    float4 v = *reinterpret_cast<const float4*>(&W[t * 4]);
    __nv_bfloat16 hx = __float2bfloat16(v.x);
    __nv_bfloat16 hy = __float2bfloat16(v.y);
    __nv_bfloat16 hz = __float2bfloat16(v.z);
    __nv_bfloat16 hw = __float2bfloat16(v.w);
    __nv_bfloat162 h01, h23, l01, l23;
    h01.x = hx; h01.y = hy; h23.x = hz; h23.y = hw;
    l01.x = __float2bfloat16(v.x - __bfloat162float(hx));
    l01.y = __float2bfloat16(v.y - __bfloat162float(hy));
    l23.x = __float2bfloat16(v.z - __bfloat162float(hz));
    l23.y = __float2bfloat16(v.w - __bfloat162float(hw));
    *reinterpret_cast<__nv_bfloat162*>(&g_Bhi[t * 4])     = h01;
    *reinterpret_cast<__nv_bfloat162*>(&g_Bhi[t * 4 + 2]) = h23;
    *reinterpret_cast<__nv_bfloat162*>(&g_Blo[t * 4])     = l01;
    *reinterpret_cast<__nv_bfloat162*>(&g_Blo[t * 4 + 2]) = l23;
}

// ---------------- tensor-core GEMM (cp.async 2-stage, static smem) -------
// C[M,1024] = A[M,Kd] @ B[Kd,1024]; block 128x128x16, 8 warps, warp 32x64
#define BM 128
#define BN 128
#define BK 16
#define ALD 24                       // bf16 row stride A smem
#define BLD 136                      // bf16 row stride B smem
#define SLD 20                       // fp32 staging stride (mult of 4)
#define A_TILE (BM * ALD)            // 3072 bf16
#define B_TILE (BK * BLD)            // 2176 bf16
#define STAGE_ELEMS (2 * A_TILE + 2 * B_TILE)   // 10496 bf16 = 20992 B

__device__ __forceinline__ void cpa16(const __nv_bfloat16* sdst,
                                      const __nv_bfloat16* gsrc, bool pred) {
    unsigned int d = (unsigned int)__cvta_generic_to_shared(sdst);
    int sz = pred ? 16 : 0;
    asm volatile("cp.async.cg.shared.global [%0], [%1], 16, %2;\n"
                 :: "r"(d), "l"(gsrc), "r"(sz));
}

template <int CSEL>
__global__ __launch_bounds__(256, 2)
void k_gemm_tc(int Kd, int M, const float* __restrict__ bias, int do_elu) {
    __shared__ __nv_bfloat16 smbuf[2 * STAGE_ELEMS];
    float* C = bufsel<CSEL>();

    const int tid  = threadIdx.x;
    const int lane = tid & 31;
    const int wid  = tid >> 5;
    const int wm   = wid >> 1;
    const int wn   = wid & 1;
    const int row0 = blockIdx.y * BM;
    const int col0 = blockIdx.x * BN;

    const int ar = tid >> 1;
    const int ac = (tid & 1) * 8;
    const int br = tid >> 4;
    const int bc = (tid & 15) * 8;
    const bool apred = (row0 + ar < M);

    wmma::fragment<wmma::accumulator, 16, 16, 16, float> acc[2][4];
#pragma unroll
    for (int i = 0; i < 2; i++)
#pragma unroll
        for (int j = 0; j < 4; j++) wmma::fill_fragment(acc[i][j], 0.f);

    const int niters = Kd / BK;

    auto load_stage = [&](int st, int kk) {
        __nv_bfloat16* base = smbuf + st * STAGE_ELEMS;
        size_t aoff = (size_t)(row0 + ar) * Kd + kk + ac;
        cpa16(base + ar * ALD + ac,          apred ? &g_Ahi[aoff] : g_Ahi, apred);
        cpa16(base + A_TILE + ar * ALD + ac, apred ? &g_Alo[aoff] : g_Alo, apred);
        size_t boff = (size_t)(kk + br) * HID + col0 + bc;
        cpa16(base + 2 * A_TILE + br * BLD + bc,          &g_Bhi[boff], true);
        cpa16(base + 2 * A_TILE + B_TILE + br * BLD + bc, &g_Blo[boff], true);
        asm volatile("cp.async.commit_group;\n" ::);
    };

    load_stage(0, 0);

    for (int it = 0; it < niters; it++) {
        if (it + 1 < niters) {
            load_stage((it + 1) & 1, (it + 1) * BK);
            asm volatile("cp.async.wait_group 1;\n" ::);
        } else {
            asm volatile("cp.async.wait_group 0;\n" ::);
        }
        __syncthreads();

        const __nv_bfloat16* cAhi = smbuf + (it & 1) * STAGE_ELEMS;
        const __nv_bfloat16* cAlo = cAhi + A_TILE;
        const __nv_bfloat16* cBhi = cAhi + 2 * A_TILE;
        const __nv_bfloat16* cBlo = cBhi + B_TILE;

        wmma::fragment<wmma::matrix_a, 16, 16, 16, __nv_bfloat16, wmma::row_major> ah[2], al[2];
        wmma::fragment<wmma::matrix_b, 16, 16, 16, __nv_bfloat16, wmma::row_major> bh[4], bl[4];
#pragma unroll
        for (int i = 0; i < 2; i++) {
            int mr = wm * 32 + i * 16;
            wmma::load_matrix_sync(ah[i], cAhi + mr * ALD, ALD);
            wmma::load_matrix_sync(al[i], cAlo + mr * ALD, ALD);
        }
#pragma unroll
        for (int j = 0; j < 4; j++) {
            int nc = wn * 64 + j * 16;
            wmma::load_matrix_sync(bh[j], cBhi + nc, BLD);
            wmma::load_matrix_sync(bl[j], cBlo + nc, BLD);
        }
#pragma unroll
        for (int i = 0; i < 2; i++)
#pragma unroll
            for (int j = 0; j < 4; j++) {
                wmma::mma_sync(acc[i][j], ah[i], bh[j], acc[i][j]);
                wmma::mma_sync(acc[i][j], ah[i], bl[j], acc[i][j]);
                wmma::mma_sync(acc[i][j], al[i], bh[j], acc[i][j]);
            }
        __syncthreads();
    }

    float* stg = reinterpret_cast<float*>(smbuf) + wid * 16 * SLD;
#pragma unroll
    for (int i = 0; i < 2; i++)
#pragma unroll
        for (int j = 0; j < 4; j++) {
            wmma::store_matrix_sync(stg, acc[i][j], SLD, wmma::mem_row_major);
            __syncwarp();
            int r0 = row0 + wm * 32 + i * 16;
            int c0 = col0 + wn * 64 + j * 16;
#pragma unroll
            for (int s = 0; s < 2; s++) {
                int slot = lane + s * 32;
                int rr = slot >> 2;
                int cc = (slot & 3) * 4;
                if (r0 + rr < M) {
                    float4 v = *reinterpret_cast<float4*>(&stg[rr * SLD + cc]);
                    v.x += bias[c0 + cc + 0];
                    v.y += bias[c0 + cc + 1];
                    v.z += bias[c0 + cc + 2];
                    v.w += bias[c0 + cc + 3];
                    if (do_elu) {
                        v.x = v.x > 0.f ? v.x : expm1f(v.x);
                        v.y = v.y > 0.f ? v.y : expm1f(v.y);
                        v.z = v.z > 0.f ? v.z : expm1f(v.z);
                        v.w = v.w > 0.f ? v.w : expm1f(v.w);
                    }
                    *reinterpret_cast<float4*>(&C[(size_t)(r0 + rr) * HID + c0 + cc]) = v;
                }
            }
            __syncwarp();
        }
}

// ---------------- GraphNorm ----------------
#define RPB 512
template <int XSEL>
__global__ void k_colsum(int ld) {
    const float* X = bufsel<XSEL>();
    int c  = blockIdx.x * blockDim.x + threadIdx.x;
    int r0 = blockIdx.y * RPB;
    int r1 = min(r0 + RPB, NN);
    float acc = 0.f;
    for (int r = r0; r < r1; r++) acc += X[(size_t)r * ld + c];
    atomicAdd(&g_sums[c], acc);
}
template <int XSEL, int YSEL>
__global__ void k_center(int ldx, int yoff, int ldy, const float* __restrict__ a) {
    const float* X = bufsel<XSEL>();
    float* Y = bufsel<YSEL>() + yoff;
    int c  = blockIdx.x * blockDim.x + threadIdx.x;
    int r0 = blockIdx.y * RPB;
    int r1 = min(r0 + RPB, NN);
    float am = a[c] * (g_sums[c] * (1.f / NN));
    float acc = 0.f;
    for (int r = r0; r < r1; r++) {
        float y = X[(size_t)r * ldx + c] - am;
        Y[(size_t)r * ldy + c] = y;
        acc += y * y;
    }
    atomicAdd(&g_sq[c], acc);
}
// DUAL=1: also emit bf16 hi/lo of the final value into g_Ahi/g_Alo
template <int YSEL, int DUAL>
__global__ void k_gnfinal(int yoff, int ld,
                          const float* __restrict__ g, const float* __restrict__ be,
                          int aoff, int ldA) {
    float* Y = bufsel<YSEL>() + yoff;
    long long t = (long long)blockIdx.x * blockDim.x + threadIdx.x;
    if (t >= (long long)NN * HID) return;
    int c = (int)(t & (HID - 1));
    int row = (int)(t >> 10);
    size_t idx = (size_t)row * ld + c;
    float s = g[c] * rsqrtf(g_sq[c] * (1.f / NN) + EPSV);
    float v = Y[idx] * s + be[c];
    Y[idx] = v;
    if (DUAL) dual_bf16(v, (size_t)row * ldA + aoff + c);
}

// ---------------- layer 3: project then Horner-propagate ----------------
// block: 256 threads = 64 outputs x 4 lanes; 16 nodes/block; W3 chunk in smem
__global__ void k_zproj(const float* __restrict__ W3) {
    __shared__ float W3s[128][65];
    int tid = threadIdx.x;
    int o = tid & 63, q = tid >> 6;
    int node0 = blockIdx.x * 16 + q * 4;
    float acc0 = 0.f, acc1 = 0.f, acc2 = 0.f, acc3 = 0.f;
    for (int chunk = 0; chunk < 8; chunk++) {
        int i0 = chunk * 128;
#pragma unroll
        for (int s = 0; s < 32; s++) {
            int e = tid + s * 256;
            int i = e >> 6, oo = e & 63;
            W3s[i][oo] = W3[(size_t)(oo >> 4) * (HID * CLS) + (size_t)(i0 + i) * CLS + (oo & 15)];
        }
        __syncthreads();
        const float* h0 = g_T1 + (size_t)(node0 + 0) * HID + i0;
        const float* h1 = g_T1 + (size_t)(node0 + 1) * HID + i0;
        const float* h2 = g_T1 + (size_t)(node0 + 2) * HID + i0;
        const float* h3 = g_T1 + (size_t)(node0 + 3) * HID + i0;
#pragma unroll 4
        for (int i = 0; i < 128; i++) {
            float wv = W3s[i][o];
            acc0 += h0[i] * wv;
            acc1 += h1[i] * wv;
            acc2 += h2[i] * wv;
            acc3 += h3[i] * wv;
        }
        __syncthreads();
    }
    g_Z[(size_t)(node0 + 0) * 64 + o] = acc0;
    g_Z[(size_t)(node0 + 1) * 64 + o] = acc1;
    g_Z[(size_t)(node0 + 2) * 64 + o] = acc2;
    g_Z[(size_t)(node0 + 3) * 64 + o] = acc3;
}
template <int USEL>
__global__ void k_add16(int zoff) {
    float* U = bufsel<USEL>();
    int t = blockIdx.x * blockDim.x + threadIdx.x;
    if (t >= NN * CLS) return;
    int n = t >> 4, c = t & 15;
    U[t] += g_Z[(size_t)n * 64 + zoff + c];
}
__global__ void k_final(float* __restrict__ out, const float* __restrict__ b3) {
    int t = blockIdx.x * blockDim.x + threadIdx.x;
    if (t >= NN * CLS) return;
    int n = t >> 4, c = t & 15;
    out[t] = g_U[t] + g_Z[(size_t)n * 64 + c] + b3[c];
}

// ---------------- host launcher ----------------
extern "C" void kernel_launch(void* const* d_in, const int* in_sizes, int n_in,
                              void* d_out, int out_size) {
    const float* x   = (const float*)d_in[0];
    const void*  ei  = d_in[1];
    const float* w   = (const float*)d_in[2];
    const float* W1  = (const float*)d_in[3];
    const float* b1  = (const float*)d_in[4];
    const float* g1  = (const float*)d_in[5];
    const float* be1 = (const float*)d_in[6];
    const float* a1  = (const float*)d_in[7];
    const float* W2  = (const float*)d_in[8];
    const float* b2  = (const float*)d_in[9];
    const float* g2  = (const float*)d_in[10];
    const float* be2 = (const float*)d_in[11];
    const float* a2  = (const float*)d_in[12];
    const float* W3  = (const float*)d_in[13];
    const float* b3  = (const float*)d_in[14];
    float* out = (float*)d_out;

    const int TB = 256;
    // --- graph preprocessing (+ ncu probe in the profiled slot) ---
    k_detect<<<1, 1>>>((const int*)ei);
    k_zero_pre<<<(NN + TB - 1) / TB, TB>>>();
    k_deg<<<(EE + TB - 1) / TB, TB>>>(ei, w);
    // PROBE: tiny GEMM on stale buffers so ncu (-s 5) profiles the GEMM kernel.
    // Deterministic per replay; output region of g_V fully overwritten later.
    k_gemm_tc<B_V><<<dim3(HID / BN, 1), 256>>>(4096, 128, b2, 1);
    k_norm<<<(NN + TB - 1) / TB, TB>>>();
    k_scan<<<1, 1024>>>();
    k_fill<<<(EE + TB - 1) / TB, TB>>>(ei, w);

    // --- layer 1: hop-concat (d=128, fused bf16 split) -> TC GEMM ---
    k_copy_x<<<(NN * FIN + TB - 1) / TB, TB>>>(x);
    for (int k = 1; k <= 3; k++)
        k_spmm<B_XCAT, B_XCAT, 1><<<(int)(((long long)NN * 128 + TB - 1) / TB), TB>>>(
            (k - 1) * 128, 512, k * 128, 512, 128, 7, k * 128, 512);
    {
        long long nB = 512LL * 1024;
        k_split_b<<<(int)((nB / 4 + TB - 1) / TB), TB>>>(W1, nB);
    }
    k_gemm_tc<B_T1><<<dim3(HID / BN, (NN + BM - 1) / BM), 256>>>(512, NN, b1, 1);

    // --- GraphNorm 1: T1 -> Hcat slice 0 (gnfinal emits bf16 too) ---
    k_zero_stats<<<(HID + TB - 1) / TB, TB>>>();
    k_colsum<B_T1><<<dim3(HID / TB, (NN + RPB - 1) / RPB), TB>>>(HID);
    k_center<B_T1, B_HCAT><<<dim3(HID / TB, (NN + RPB - 1) / RPB), TB>>>(HID, 0, 4096, a1);
    k_gnfinal<B_HCAT, 1><<<(int)(((long long)NN * HID + TB - 1) / TB), TB>>>(
        0, 4096, g1, be1, 0, 4096);

    // --- layer 2: hop-concat (d=1024, fused bf16 split) -> TC GEMM ---
    for (int k = 1; k <= 3; k++)
        k_spmm<B_HCAT, B_HCAT, 1><<<(int)(((long long)NN * 1024 + TB - 1) / TB), TB>>>(
            (k - 1) * 1024, 4096, k * 1024, 4096, 1024, 10, k * 1024, 4096);
    {
        long long nB = 4096LL * 1024;
        k_split_b<<<(int)((nB / 4 + TB - 1) / TB), TB>>>(W2, nB);
    }
    k_gemm_tc<B_T1><<<dim3(HID / BN, (NN + BM - 1) / BM), 256>>>(4096, NN, b2, 1);

    // --- GraphNorm 2: in-place on T1 (h2) ---
    k_zero_stats<<<(HID + TB - 1) / TB, TB>>>();
    k_colsum<B_T1><<<dim3(HID / TB, (NN + RPB - 1) / RPB), TB>>>(HID);
    k_center<B_T1, B_T1><<<dim3(HID / TB, (NN + RPB - 1) / RPB), TB>>>(HID, 0, HID, a2);
    k_gnfinal<B_T1, 0><<<(int)(((long long)NN * HID + TB - 1) / TB), TB>>>(
        0, HID, g2, be2, 0, 0);

    // --- layer 3: project first (smem-tiled), then Horner over A ---
    k_zproj<<<NN / 16, 256>>>(W3);
    k_spmm<B_Z, B_U, 0><<<(NN * CLS + TB - 1) / TB, TB>>>(48, 64, 0, 16, 16, 4, 0, 0);
    k_add16<B_U><<<(NN * CLS + TB - 1) / TB, TB>>>(32);
    k_spmm<B_U, B_V, 0><<<(NN * CLS + TB - 1) / TB, TB>>>(0, 16, 0, 16, 16, 4, 0, 0);
    k_add16<B_V><<<(NN * CLS + TB - 1) / TB, TB>>>(16);
    k_spmm<B_V, B_U, 0><<<(NN * CLS + TB - 1) / TB, TB>>>(0, 16, 0, 16, 16, 4, 0, 0);
    k_final<<<(NN * CLS + TB - 1) / TB, TB>>>(out, b3);
}